// round 8
// baseline (speedup 1.0000x reference)
#include <cuda_runtime.h>
#include <cuda_bf16.h>
#include <cstdint>

#define EIN 512
#define H   96
#define BSZ 64
#define QLEN 128
#define PLEN 196

// ---------------- scratch (device globals; zero-initialized) ----------------
__device__ float g_Vt [BSZ*H*QLEN];   // [c][h][q] h-major fp32
__device__ float g_t [BSZ*H];
__device__ float g_d [BSZ*H];
__device__ float g_v [BSZ*H];

// bf16 hi/lo split operands (plain row-major [b][row][h])
__device__ __nv_bfloat16 g_Qhi[BSZ*QLEN*H];
__device__ __nv_bfloat16 g_Qlo[BSZ*QLEN*H];
__device__ __nv_bfloat16 g_Khi[BSZ*QLEN*H];
__device__ __nv_bfloat16 g_Klo[BSZ*QLEN*H];
__device__ __nv_bfloat16 g_Ahi[BSZ*QLEN*H];   // t_tok
__device__ __nv_bfloat16 g_Alo[BSZ*QLEN*H];
__device__ __nv_bfloat16 g_Bhi[BSZ*PLEN*H];   // v_patch
__device__ __nv_bfloat16 g_Blo[BSZ*PLEN*H];

// ---------------- PTX helpers ----------------
__device__ __forceinline__ uint32_t smem_u32(const void* p) {
    uint32_t a;
    asm("{ .reg .u64 t; cvta.to.shared.u64 t, %1; cvt.u32.u64 %0, t; }"
        : "=r"(a) : "l"(p));
    return a;
}
__device__ __forceinline__ void ldsm_x4(uint32_t* r, uint32_t addr) {
    asm volatile("ldmatrix.sync.aligned.m8n8.x4.shared.b16 {%0,%1,%2,%3}, [%4];"
        : "=r"(r[0]),"=r"(r[1]),"=r"(r[2]),"=r"(r[3]) : "r"(addr));
}
__device__ __forceinline__ void mma16816(float* d, const uint32_t* a, const uint32_t* b) {
    asm volatile("mma.sync.aligned.m16n8k16.row.col.f32.bf16.bf16.f32 "
        "{%0,%1,%2,%3}, {%4,%5,%6,%7}, {%8,%9}, {%0,%1,%2,%3};"
        : "+f"(d[0]),"+f"(d[1]),"+f"(d[2]),"+f"(d[3])
        : "r"(a[0]),"r"(a[1]),"r"(a[2]),"r"(a[3]), "r"(b[0]),"r"(b[1]));
}

// ---------------- K1: batched projection (all 8), fused l2n / transpose / bf16-split ----------------
struct ProjArgs {
    const float* X[8];
    const float* W[8];
    const float* Bv[8];
    float*       Out[8];
    void*        Out2[8];
    int          tile_start[9];
    int          l2n[8];
    int          L[8];       // >0: fp32 transposed [row/L][96][L]
    int          mode[8];    // 0: fp32, 1: bf16 split 128 rows/b, 2: bf16 split 196 rows/c
};

__global__ __launch_bounds__(256) void proj_all(ProjArgs pa)
{
    __shared__ float Xs[64*33];
    __shared__ float Ws[96*33];

    int bid = blockIdx.x;
    int mi = 0;
#pragma unroll
    for (int i=1;i<8;i++) if (bid >= pa.tile_start[i]) mi = i;
    int tile = bid - pa.tile_start[mi];

    const float* Xb   = pa.X[mi] + (long)tile*64*EIN;
    const float* W    = pa.W[mi];
    const float* bias = pa.Bv[mi];

    int tid = threadIdx.x;
    int tm = tid >> 4, tn = tid & 15;
    int m0 = tm*4,  n0 = tn*6;

    float acc[4][6];
#pragma unroll
    for (int i=0;i<4;i++)
#pragma unroll
        for (int j=0;j<6;j++) acc[i][j]=0.f;

    for (int k0=0;k0<EIN;k0+=32) {
        __syncthreads();
        for (int idx=tid; idx<64*32; idx+=256) {
            int m = idx>>5, kk = idx&31;
            Xs[m*33+kk] = Xb[m*EIN + k0 + kk];
        }
        for (int idx=tid; idx<96*32; idx+=256) {
            int n = idx>>5, kk = idx&31;
            Ws[n*33+kk] = W[n*EIN + k0 + kk];
        }
        __syncthreads();
#pragma unroll 8
        for (int kk=0;kk<32;kk++) {
            float a[4], b[6];
#pragma unroll
            for (int i=0;i<4;i++) a[i]=Xs[(m0+i)*33+kk];
#pragma unroll
            for (int j=0;j<6;j++) b[j]=Ws[(n0+j)*33+kk];
#pragma unroll
            for (int i=0;i<4;i++)
#pragma unroll
                for (int j=0;j<6;j++) acc[i][j] += a[i]*b[j];
        }
    }

#pragma unroll
    for (int i=0;i<4;i++)
#pragma unroll
        for (int j=0;j<6;j++) acc[i][j] += bias[n0+j];

    if (pa.l2n[mi]) {
        __syncthreads();
#pragma unroll
        for (int i=0;i<4;i++) {
            float ss = 0.f;
#pragma unroll
            for (int j=0;j<6;j++) ss += acc[i][j]*acc[i][j];
            Xs[(m0+i)*17 + tn] = ss;
        }
        __syncthreads();
        if (tid < 64) {
            float s = 0.f;
#pragma unroll
            for (int t=0;t<16;t++) s += Xs[tid*17+t];
            Ws[tid] = 1.f / fmaxf(sqrtf(s), 1e-6f);
        }
        __syncthreads();
#pragma unroll
        for (int i=0;i<4;i++) {
            float sc = Ws[m0+i];
#pragma unroll
            for (int j=0;j<6;j++) acc[i][j] *= sc;
        }
    }

    int mode = pa.mode[mi];
    if (mode) {
        int perlen = (mode==1) ? 128 : 196;
        __nv_bfloat16* hiB = (__nv_bfloat16*)pa.Out[mi];
        __nv_bfloat16* loB = (__nv_bfloat16*)pa.Out2[mi];
#pragma unroll
        for (int i=0;i<4;i++) {
            int gr = tile*64 + m0 + i;
            int bb = gr / perlen, rr = gr - bb*perlen;
            long base = ((long)bb*perlen + rr)*H + n0;
#pragma unroll
            for (int j=0;j<6;j++) {
                float x = acc[i][j];
                __nv_bfloat16 hv = __float2bfloat16(x);
                __nv_bfloat16 lv = __float2bfloat16(x - __bfloat162float(hv));
                hiB[base+j] = hv;
                loB[base+j] = lv;
            }
        }
    } else {
        int L = pa.L[mi];
        if (L > 0) {
            float* O = pa.Out[mi];
#pragma unroll
            for (int i=0;i<4;i++) {
                int gr = tile*64 + m0 + i;
                int bb = gr / L, pp = gr - bb*L;
                float* base = O + (long)bb*H*L + pp;
#pragma unroll
                for (int j=0;j<6;j++) base[(n0+j)*L] = acc[i][j];
            }
        } else {
            float* O = pa.Out[mi] + (long)tile*64*H;
#pragma unroll
            for (int i=0;i<4;i++)
#pragma unroll
                for (int j=0;j<6;j++) O[(m0+i)*H + n0 + j] = acc[i][j];
        }
    }
}

// ---------------- K2: out[i,j] = 0.5*( t[i].d[j] + t[i].v[j] ) ----------------
__global__ void gg_kernel(float* __restrict__ out)
{
    int i = blockIdx.x, j = threadIdx.x;
    const float* ti = g_t + i*H;
    const float* dj = g_d + j*H;
    const float* vj = g_v + j*H;
    float s = 0.f;
#pragma unroll 8
    for (int h=0;h<H;h++) s += ti[h]*(dj[h]+vj[h]);
    out[i*64+j] = 0.5f*s;
}

// ---------------- K3: TGL via mma.sync, softmax in registers ----------------
#define TRP 104
#define TOFF_QHI 0
#define TOFF_QLO (TOFF_QHI + 128*TRP*2)
#define TOFF_KHI (TOFF_QLO + 128*TRP*2)
#define TOFF_KLO (TOFF_KHI + 128*TRP*2)
#define TOFF_CS  (TOFF_KLO + 128*TRP*2)      // colsum [8][128] f32
#define TOFF_WV  (TOFF_CS + 8*128*4)         // [128] f32
#define TOFF_CTX (TOFF_WV + 128*4)           // [96] f32
#define SM_TGL   (TOFF_CTX + 96*4 + 16)

__global__ __launch_bounds__(256,1) void tgl_mma(
    const float* __restrict__ lng, const float* __restrict__ lnb,
    float* __restrict__ out)
{
    extern __shared__ char smem[];
    uint32_t sb = smem_u32(smem);
    int tid = threadIdx.x;
    int wid = tid >> 5, lane = tid & 31;
    int b = blockIdx.y, c = blockIdx.x;

    {
        const uint4* Qh = (const uint4*)(g_Qhi + (long)b*QLEN*H);
        const uint4* Ql = (const uint4*)(g_Qlo + (long)b*QLEN*H);
        const uint4* Kh = (const uint4*)(g_Khi + (long)c*QLEN*H);
        const uint4* Kl = (const uint4*)(g_Klo + (long)c*QLEN*H);
        uint4* dQh = (uint4*)(smem + TOFF_QHI);
        uint4* dQl = (uint4*)(smem + TOFF_QLO);
        uint4* dKh = (uint4*)(smem + TOFF_KHI);
        uint4* dKl = (uint4*)(smem + TOFF_KLO);
        for (int idx=tid; idx<128*12; idx+=256) {
            int r = idx/12, q = idx%12;
            dQh[r*13+q] = Qh[idx];
            dQl[r*13+q] = Ql[idx];
            dKh[r*13+q] = Kh[idx];
            dKl[r*13+q] = Kl[idx];
        }
    }
    __syncthreads();

    // A (Q) fragments
    int m0 = wid*16;
    uint32_t qhi[6][4], qlo[6][4];
    {
        int rrow = m0 + (lane & 7) + ((lane >> 3) & 1) * 8;
        int rchk = ((lane >> 4) & 1) * 16;
#pragma unroll
        for (int ks=0; ks<6; ks++) {
            ldsm_x4(qhi[ks], sb + TOFF_QHI + rrow*(TRP*2) + ks*32 + rchk);
            ldsm_x4(qlo[ks], sb + TOFF_QLO + rrow*(TRP*2) + ks*32 + rchk);
        }
    }

    // GEMM: 16 n-tiles; 3 independent accumulator chains; B via ldsm_x4 (2 k-steps)
    float acc[16][4];
    int brow = lane & 7;
    int bqd  = ((lane >> 3) & 3) * 16;
#pragma unroll
    for (int nt=0; nt<16; nt++) {
        float a0[4]={0.f,0.f,0.f,0.f}, a1[4]={0.f,0.f,0.f,0.f}, a2[4]={0.f,0.f,0.f,0.f};
        uint32_t bh_addr = sb + TOFF_KHI + (nt*8+brow)*(TRP*2) + bqd;
        uint32_t bl_addr = sb + TOFF_KLO + (nt*8+brow)*(TRP*2) + bqd;
#pragma unroll
        for (int ks2=0; ks2<3; ks2++) {
            uint32_t kh[4], kl[4];
            ldsm_x4(kh, bh_addr + ks2*64);
            ldsm_x4(kl, bl_addr + ks2*64);
            mma16816(a0, qhi[2*ks2],   kh);
            mma16816(a1, qlo[2*ks2],   kh);
            mma16816(a2, qhi[2*ks2],   kl);
            mma16816(a0, qhi[2*ks2+1], kh+2);
            mma16816(a1, qlo[2*ks2+1], kh+2);
            mma16816(a2, qhi[2*ks2+1], kl+2);
        }
#pragma unroll
        for (int i=0;i<4;i++) acc[nt][i] = a0[i]+a1[i]+a2[i];
    }

    // in-register row softmax
    const float SC = 0.1020620726159658f;   // 1/sqrt(96)
    float m1 = -1e30f, m2 = -1e30f;
#pragma unroll
    for (int nt=0; nt<16; nt++) {
        m1 = fmaxf(m1, fmaxf(acc[nt][0], acc[nt][1]));
        m2 = fmaxf(m2, fmaxf(acc[nt][2], acc[nt][3]));
    }
    m1 = fmaxf(m1, __shfl_xor_sync(0xffffffffu, m1, 1));
    m1 = fmaxf(m1, __shfl_xor_sync(0xffffffffu, m1, 2));
    m2 = fmaxf(m2, __shfl_xor_sync(0xffffffffu, m2, 1));
    m2 = fmaxf(m2, __shfl_xor_sync(0xffffffffu, m2, 2));

    float s1 = 0.f, s2 = 0.f;
#pragma unroll
    for (int nt=0; nt<16; nt++) {
        float e0 = __expf((acc[nt][0]-m1)*SC);
        float e1 = __expf((acc[nt][1]-m1)*SC);
        float e2 = __expf((acc[nt][2]-m2)*SC);
        float e3 = __expf((acc[nt][3]-m2)*SC);
        acc[nt][0]=e0; acc[nt][1]=e1; acc[nt][2]=e2; acc[nt][3]=e3;
        s1 += e0+e1; s2 += e2+e3;
    }
    s1 += __shfl_xor_sync(0xffffffffu, s1, 1);
    s1 += __shfl_xor_sync(0xffffffffu, s1, 2);
    s2 += __shfl_xor_sync(0xffffffffu, s2, 1);
    s2 += __shfl_xor_sync(0xffffffffu, s2, 2);
    float inv1 = 1.f/s1, inv2 = 1.f/s2;

    float* colsum = (float*)(smem + TOFF_CS);
#pragma unroll
    for (int nt=0; nt<16; nt++) {
        float v0 = acc[nt][0]*inv1 + acc[nt][2]*inv2;
        float v1 = acc[nt][1]*inv1 + acc[nt][3]*inv2;
#pragma unroll
        for (int o=4; o<32; o<<=1) {
            v0 += __shfl_xor_sync(0xffffffffu, v0, o);
            v1 += __shfl_xor_sync(0xffffffffu, v1, o);
        }
        if (lane < 4) {
            colsum[wid*128 + nt*8 + lane*2]     = v0;
            colsum[wid*128 + nt*8 + lane*2 + 1] = v1;
        }
    }
    __syncthreads();

    float* wv = (float*)(smem + TOFF_WV);
    if (tid < 128) {
        float s = 0.f;
#pragma unroll
        for (int w=0; w<8; w++) s += colsum[w*128 + tid];
        wv[tid] = s * (1.f/128.f);
    }
    __syncthreads();

    float* ctxs = (float*)(smem + TOFF_CTX);
    if (tid < 96) {
        const float* Vr = g_Vt + (long)c*H*QLEN + tid*QLEN;
        float s = 0.f;
#pragma unroll
        for (int k4=0;k4<QLEN/4;k4++) {
            float4 v = ((const float4*)Vr)[k4];
            s += wv[k4*4]*v.x + wv[k4*4+1]*v.y + wv[k4*4+2]*v.z + wv[k4*4+3]*v.w;
        }
        ctxs[tid] = s;
    }
    __syncthreads();

    if (tid < 32) {
        float x0=ctxs[tid], x1=ctxs[tid+32], x2=ctxs[tid+64];
        float mu = x0+x1+x2;
#pragma unroll
        for (int o=16;o;o>>=1) mu += __shfl_xor_sync(0xffffffffu,mu,o);
        mu *= (1.f/96.f);
        float d0=x0-mu, d1=x1-mu, d2=x2-mu;
        float var = d0*d0 + d1*d1 + d2*d2;
#pragma unroll
        for (int o=16;o;o>>=1) var += __shfl_xor_sync(0xffffffffu,var,o);
        var *= (1.f/96.f);
        float rstd = rsqrtf(var + 1e-5f);
        float n0v = d0*rstd*lng[tid]    + lnb[tid];
        float n1v = d1*rstd*lng[tid+32] + lnb[tid+32];
        float n2v = d2*rstd*lng[tid+64] + lnb[tid+64];
        float ss = n0v*n0v + n1v*n1v + n2v*n2v;
#pragma unroll
        for (int o=16;o;o>>=1) ss += __shfl_xor_sync(0xffffffffu,ss,o);
        float sc = 1.f / fmaxf(sqrtf(ss), 1e-6f);
        const float* db = g_d + b*H;
        float dt = db[tid]*n0v + db[tid+32]*n1v + db[tid+64]*n2v;
#pragma unroll
        for (int o=16;o;o>>=1) dt += __shfl_xor_sync(0xffffffffu,dt,o);
        if (tid==0) out[b*64+c] += 0.5f * (dt*sc);
    }
}

// ---------------- K4: CLL via mma.sync bf16 split-precision ----------------
#define RPAD 104
#define OFF_AHI 0
#define OFF_ALO (OFF_AHI + 128*RPAD*2)
#define OFF_BHI (OFF_ALO + 128*RPAD*2)
#define OFF_BLO (OFF_BHI + 200*RPAD*2)
#define OFF_RED (OFF_BLO + 200*RPAD*2)
#define SM_CLL  (OFF_RED + 64)

__global__ __launch_bounds__(256,1) void cll_mma(float* __restrict__ out)
{
    extern __shared__ char smem[];
    uint32_t sb = smem_u32(smem);
    int tid = threadIdx.x;
    int wid = tid >> 5, lane = tid & 31;
    int b = blockIdx.y, c = blockIdx.x;

    {
        const uint4* Ah = (const uint4*)(g_Ahi + (long)b*QLEN*H);
        const uint4* Al = (const uint4*)(g_Alo + (long)b*QLEN*H);
        uint4* dAh = (uint4*)(smem + OFF_AHI);
        uint4* dAl = (uint4*)(smem + OFF_ALO);
        for (int idx=tid; idx<128*12; idx+=256) {
            int r = idx/12, q = idx%12;
            dAh[r*13+q] = Ah[idx];
            dAl[r*13+q] = Al[idx];
        }
        const uint4* Bh = (const uint4*)(g_Bhi + (long)c*PLEN*H);
        const uint4* Bl = (const uint4*)(g_Blo + (long)c*PLEN*H);
        uint4* dBh = (uint4*)(smem + OFF_BHI);
        uint4* dBl = (uint4*)(smem + OFF_BLO);
        for (int idx=tid; idx<196*12; idx+=256) {
            int r = idx/12, q = idx%12;
            dBh[r*13+q] = Bh[idx];
            dBl[r*13+q] = Bl[idx];
        }
        uint4 z = make_uint4(0,0,0,0);
        for (int idx=tid; idx<4*13; idx+=256) {
            int r = 196 + idx/13, q = idx%13;
            dBh[r*13+q] = z;
            dBl[r*13+q] = z;
        }
    }
    __syncthreads();

    int m0 = wid*16;
    uint32_t ahi[6][4], alo[6][4];
    {
        int rrow = m0 + (lane & 7) + ((lane >> 3) & 1) * 8;
        int rchk = ((lane >> 4) & 1) * 16;
#pragma unroll
        for (int ks=0; ks<6; ks++) {
            ldsm_x4(ahi[ks], sb + OFF_AHI + rrow*(RPAD*2) + ks*32 + rchk);
            ldsm_x4(alo[ks], sb + OFF_ALO + rrow*(RPAD*2) + ks*32 + rchk);
        }
    }

    float mbest = -1e30f;
    int brow = lane & 7;
    int bqd  = ((lane >> 3) & 3) * 16;
    for (int nt=0; nt<25; nt++) {
        float a0[4]={0.f,0.f,0.f,0.f}, a1[4]={0.f,0.f,0.f,0.f}, a2[4]={0.f,0.f,0.f,0.f};
        int n0 = nt*8;
        uint32_t baddr_h = sb + OFF_BHI + (n0+brow)*(RPAD*2) + bqd;
        uint32_t baddr_l = sb + OFF_BLO + (n0+brow)*(RPAD*2) + bqd;
#pragma unroll
        for (int ks2=0; ks2<3; ks2++) {
            uint32_t bh[4], bl[4];
            ldsm_x4(bh, baddr_h + ks2*64);
            ldsm_x4(bl, baddr_l + ks2*64);
            mma16816(a0, ahi[2*ks2],   bh);
            mma16816(a1, alo[2*ks2],   bh);
            mma16816(a2, ahi[2*ks2],   bl);
            mma16816(a0, ahi[2*ks2+1], bh+2);
            mma16816(a1, alo[2*ks2+1], bh+2);
            mma16816(a2, ahi[2*ks2+1], bl+2);
        }
        float v0 = a0[0]+a1[0]+a2[0];
        float v1 = a0[1]+a1[1]+a2[1];
        float v2 = a0[2]+a1[2]+a2[2];
        float v3 = a0[3]+a1[3]+a2[3];
        int col0 = n0 + (lane & 3)*2;
        if (col0 < PLEN)   mbest = fmaxf(mbest, fmaxf(v0, v2));
        if (col0+1 < PLEN) mbest = fmaxf(mbest, fmaxf(v1, v3));
    }

#pragma unroll
    for (int o=16;o;o>>=1) mbest = fmaxf(mbest, __shfl_xor_sync(0xffffffffu,mbest,o));
    float* red = (float*)(smem + OFF_RED);
    if (lane == 0) red[wid] = mbest;
    __syncthreads();
    if (tid == 0) {
        float m = red[0];
#pragma unroll
        for (int w=1;w<8;w++) m = fmaxf(m, red[w]);
        out[b*64+c] += 0.5f*m;
    }
}

// ---------------- host ----------------
extern "C" void kernel_launch(void* const* d_in, const int* in_sizes, int n_in,
                              void* d_out, int out_size)
{
    const float* z_d_cls = (const float*)d_in[0];
    const float* Z_d_tok = (const float*)d_in[1];
    const float* z_t_cls = (const float*)d_in[2];
    const float* Z_t_tok = (const float*)d_in[3];
    const float* z_v_cls = (const float*)d_in[4];
    const float* Z_v_pat = (const float*)d_in[5];
    const float *W_t_cls=(const float*)d_in[6],  *b_t_cls=(const float*)d_in[7];
    const float *W_d_cls=(const float*)d_in[8],  *b_d_cls=(const float*)d_in[9];
    const float *W_v_cls=(const float*)d_in[10], *b_v_cls=(const float*)d_in[11];
    const float *W_t_tok=(const float*)d_in[12], *b_t_tok=(const float*)d_in[13];
    const float *W_v_pat=(const float*)d_in[14], *b_v_pat=(const float*)d_in[15];
    const float *W_q=(const float*)d_in[16], *b_q=(const float*)d_in[17];
    const float *W_k=(const float*)d_in[18], *b_k=(const float*)d_in[19];
    const float *W_v=(const float*)d_in[20], *b_v=(const float*)d_in[21];
    const float *ln_g=(const float*)d_in[22], *ln_b=(const float*)d_in[23];
    float* out = (float*)d_out;

    float *Vp,*tp,*dp,*vp;
    void *qhi,*qlo,*khi,*klo,*ahi,*alo,*bhi,*blo;
    cudaGetSymbolAddress((void**)&Vp,  g_Vt);
    cudaGetSymbolAddress((void**)&tp,  g_t);
    cudaGetSymbolAddress((void**)&dp,  g_d);
    cudaGetSymbolAddress((void**)&vp,  g_v);
    cudaGetSymbolAddress(&qhi, g_Qhi);
    cudaGetSymbolAddress(&qlo, g_Qlo);
    cudaGetSymbolAddress(&khi, g_Khi);
    cudaGetSymbolAddress(&klo, g_Klo);
    cudaGetSymbolAddress(&ahi, g_Ahi);
    cudaGetSymbolAddress(&alo, g_Alo);
    cudaGetSymbolAddress(&bhi, g_Bhi);
    cudaGetSymbolAddress(&blo, g_Blo);

    cudaFuncSetAttribute(tgl_mma, cudaFuncAttributeMaxDynamicSharedMemorySize, SM_TGL);
    cudaFuncSetAttribute(cll_mma, cudaFuncAttributeMaxDynamicSharedMemorySize, SM_CLL);

    ProjArgs pa;
    for (int i=0;i<8;i++) { pa.Out2[i]=nullptr; pa.mode[i]=0; pa.L[i]=0; pa.l2n[i]=0; }
    pa.X[0]=Z_d_tok; pa.W[0]=W_q;     pa.Bv[0]=b_q;     pa.Out[0]=(float*)qhi; pa.Out2[0]=qlo; pa.mode[0]=1;
    pa.X[1]=Z_t_tok; pa.W[1]=W_k;     pa.Bv[1]=b_k;     pa.Out[1]=(float*)khi; pa.Out2[1]=klo; pa.mode[1]=1;
    pa.X[2]=Z_t_tok; pa.W[2]=W_v;     pa.Bv[2]=b_v;     pa.Out[2]=Vp;  pa.L[2]=QLEN;
    pa.X[3]=Z_t_tok; pa.W[3]=W_t_tok; pa.Bv[3]=b_t_tok; pa.Out[3]=(float*)ahi; pa.Out2[3]=alo; pa.l2n[3]=1; pa.mode[3]=1;
    pa.X[4]=Z_v_pat; pa.W[4]=W_v_pat; pa.Bv[4]=b_v_pat; pa.Out[4]=(float*)bhi; pa.Out2[4]=blo; pa.l2n[4]=1; pa.mode[4]=2;
    pa.X[5]=z_t_cls; pa.W[5]=W_t_cls; pa.Bv[5]=b_t_cls; pa.Out[5]=tp;  pa.l2n[5]=1;
    pa.X[6]=z_d_cls; pa.W[6]=W_d_cls; pa.Bv[6]=b_d_cls; pa.Out[6]=dp;  pa.l2n[6]=1;
    pa.X[7]=z_v_cls; pa.W[7]=W_v_cls; pa.Bv[7]=b_v_cls; pa.Out[7]=vp;  pa.l2n[7]=1;
    int nt[8] = {128,128,128,128,196,1,1,1};
    pa.tile_start[0]=0;
    for (int i=0;i<8;i++) pa.tile_start[i+1]=pa.tile_start[i]+nt[i];

    proj_all<<<pa.tile_start[8],256>>>(pa);

    gg_kernel<<<64,64>>>(out);
    tgl_mma<<<dim3(64,64),256,SM_TGL>>>(ln_g, ln_b, out);
    cll_mma<<<dim3(64,64),256,SM_CLL>>>(out);
}

// round 9
// speedup vs baseline: 1.1109x; 1.1109x over previous
#include <cuda_runtime.h>
#include <cuda_bf16.h>
#include <cstdint>

#define EIN 512
#define H   96
#define BSZ 64
#define QLEN 128
#define PLEN 196

// ---------------- scratch (device globals; zero-initialized) ----------------
__device__ float g_Vt [BSZ*H*QLEN];   // [c][h][q] h-major fp32
__device__ float g_t [BSZ*H];
__device__ float g_d [BSZ*H];
__device__ float g_v [BSZ*H];

// bf16 hi/lo split operands (plain row-major [b][row][h])
__device__ __nv_bfloat16 g_Qhi[BSZ*QLEN*H];
__device__ __nv_bfloat16 g_Qlo[BSZ*QLEN*H];
__device__ __nv_bfloat16 g_Khi[BSZ*QLEN*H];
__device__ __nv_bfloat16 g_Klo[BSZ*QLEN*H];
__device__ __nv_bfloat16 g_Ahi[BSZ*QLEN*H];   // t_tok
__device__ __nv_bfloat16 g_Alo[BSZ*QLEN*H];
__device__ __nv_bfloat16 g_Bhi[BSZ*PLEN*H];   // v_patch
__device__ __nv_bfloat16 g_Blo[BSZ*PLEN*H];

// ---------------- PTX helpers ----------------
__device__ __forceinline__ uint32_t smem_u32(const void* p) {
    uint32_t a;
    asm("{ .reg .u64 t; cvta.to.shared.u64 t, %1; cvt.u32.u64 %0, t; }"
        : "=r"(a) : "l"(p));
    return a;
}
__device__ __forceinline__ void ldsm_x4(uint32_t* r, uint32_t addr) {
    asm volatile("ldmatrix.sync.aligned.m8n8.x4.shared.b16 {%0,%1,%2,%3}, [%4];"
        : "=r"(r[0]),"=r"(r[1]),"=r"(r[2]),"=r"(r[3]) : "r"(addr));
}
__device__ __forceinline__ void mma16816(float* d, const uint32_t* a, const uint32_t* b) {
    asm volatile("mma.sync.aligned.m16n8k16.row.col.f32.bf16.bf16.f32 "
        "{%0,%1,%2,%3}, {%4,%5,%6,%7}, {%8,%9}, {%0,%1,%2,%3};"
        : "+f"(d[0]),"+f"(d[1]),"+f"(d[2]),"+f"(d[3])
        : "r"(a[0]),"r"(a[1]),"r"(a[2]),"r"(a[3]), "r"(b[0]),"r"(b[1]));
}

// ---------------- K1: batched projection (all 8), fused l2n / transpose / bf16-split ----------------
struct ProjArgs {
    const float* X[8];
    const float* W[8];
    const float* Bv[8];
    float*       Out[8];
    void*        Out2[8];
    int          tile_start[9];
    int          l2n[8];
    int          L[8];       // >0: fp32 transposed [row/L][96][L]
    int          mode[8];    // 0: fp32, 1: bf16 split 128 rows/b, 2: bf16 split 196 rows/c
};

__global__ __launch_bounds__(256) void proj_all(ProjArgs pa)
{
    __shared__ float Xs[64*33];
    __shared__ float Ws[96*33];

    int bid = blockIdx.x;
    int mi = 0;
#pragma unroll
    for (int i=1;i<8;i++) if (bid >= pa.tile_start[i]) mi = i;
    int tile = bid - pa.tile_start[mi];

    const float* Xb   = pa.X[mi] + (long)tile*64*EIN;
    const float* W    = pa.W[mi];
    const float* bias = pa.Bv[mi];

    int tid = threadIdx.x;
    int tm = tid >> 4, tn = tid & 15;
    int m0 = tm*4,  n0 = tn*6;

    float acc[4][6];
#pragma unroll
    for (int i=0;i<4;i++)
#pragma unroll
        for (int j=0;j<6;j++) acc[i][j]=0.f;

    for (int k0=0;k0<EIN;k0+=32) {
        __syncthreads();
        for (int idx=tid; idx<64*32; idx+=256) {
            int m = idx>>5, kk = idx&31;
            Xs[m*33+kk] = Xb[m*EIN + k0 + kk];
        }
        for (int idx=tid; idx<96*32; idx+=256) {
            int n = idx>>5, kk = idx&31;
            Ws[n*33+kk] = W[n*EIN + k0 + kk];
        }
        __syncthreads();
#pragma unroll 8
        for (int kk=0;kk<32;kk++) {
            float a[4], b[6];
#pragma unroll
            for (int i=0;i<4;i++) a[i]=Xs[(m0+i)*33+kk];
#pragma unroll
            for (int j=0;j<6;j++) b[j]=Ws[(n0+j)*33+kk];
#pragma unroll
            for (int i=0;i<4;i++)
#pragma unroll
                for (int j=0;j<6;j++) acc[i][j] += a[i]*b[j];
        }
    }

#pragma unroll
    for (int i=0;i<4;i++)
#pragma unroll
        for (int j=0;j<6;j++) acc[i][j] += bias[n0+j];

    if (pa.l2n[mi]) {
        __syncthreads();
#pragma unroll
        for (int i=0;i<4;i++) {
            float ss = 0.f;
#pragma unroll
            for (int j=0;j<6;j++) ss += acc[i][j]*acc[i][j];
            Xs[(m0+i)*17 + tn] = ss;
        }
        __syncthreads();
        if (tid < 64) {
            float s = 0.f;
#pragma unroll
            for (int t=0;t<16;t++) s += Xs[tid*17+t];
            Ws[tid] = 1.f / fmaxf(sqrtf(s), 1e-6f);
        }
        __syncthreads();
#pragma unroll
        for (int i=0;i<4;i++) {
            float sc = Ws[m0+i];
#pragma unroll
            for (int j=0;j<6;j++) acc[i][j] *= sc;
        }
    }

    int mode = pa.mode[mi];
    if (mode) {
        int perlen = (mode==1) ? 128 : 196;
        __nv_bfloat16* hiB = (__nv_bfloat16*)pa.Out[mi];
        __nv_bfloat16* loB = (__nv_bfloat16*)pa.Out2[mi];
#pragma unroll
        for (int i=0;i<4;i++) {
            int gr = tile*64 + m0 + i;
            int bb = gr / perlen, rr = gr - bb*perlen;
            long base = ((long)bb*perlen + rr)*H + n0;
#pragma unroll
            for (int j=0;j<6;j++) {
                float x = acc[i][j];
                __nv_bfloat16 hv = __float2bfloat16(x);
                __nv_bfloat16 lv = __float2bfloat16(x - __bfloat162float(hv));
                hiB[base+j] = hv;
                loB[base+j] = lv;
            }
        }
    } else {
        int L = pa.L[mi];
        if (L > 0) {
            float* O = pa.Out[mi];
#pragma unroll
            for (int i=0;i<4;i++) {
                int gr = tile*64 + m0 + i;
                int bb = gr / L, pp = gr - bb*L;
                float* base = O + (long)bb*H*L + pp;
#pragma unroll
                for (int j=0;j<6;j++) base[(n0+j)*L] = acc[i][j];
            }
        } else {
            float* O = pa.Out[mi] + (long)tile*64*H;
#pragma unroll
            for (int i=0;i<4;i++)
#pragma unroll
                for (int j=0;j<6;j++) O[(m0+i)*H + n0 + j] = acc[i][j];
        }
    }
}

// ---------------- K2: out[i,j] = 0.5*( t[i].d[j] + t[i].v[j] ) ----------------
__global__ void gg_kernel(float* __restrict__ out)
{
    int i = blockIdx.x, j = threadIdx.x;
    const float* ti = g_t + i*H;
    const float* dj = g_d + j*H;
    const float* vj = g_v + j*H;
    float s = 0.f;
#pragma unroll 8
    for (int h=0;h<H;h++) s += ti[h]*(dj[h]+vj[h]);
    out[i*64+j] = 0.5f*s;
}

// ---------------- K3: TGL via mma.sync (512 thr, 16 warps, 2-pass softmax) ----------------
#define TRP 104
#define TOFF_QHI 0
#define TOFF_QLO (TOFF_QHI + 128*TRP*2)
#define TOFF_KHI (TOFF_QLO + 128*TRP*2)
#define TOFF_KLO (TOFF_KHI + 128*TRP*2)
#define TOFF_PM  (TOFF_KLO + 128*TRP*2)      // [2][128] f32 partial row max
#define TOFF_PS  (TOFF_PM + 2*128*4)         // [2][128] f32 partial row sum
#define TOFF_CS  (TOFF_PS + 2*128*4)         // [8][128] f32 colsum per band
#define TOFF_WV  (TOFF_CS + 8*128*4)         // [128] f32
#define TOFF_CTX (TOFF_WV + 128*4)           // [96] f32
#define SM_TGL   (TOFF_CTX + 96*4 + 16)

__global__ __launch_bounds__(512,1) void tgl_mma(
    const float* __restrict__ lng, const float* __restrict__ lnb,
    float* __restrict__ out)
{
    extern __shared__ char smem[];
    uint32_t sb = smem_u32(smem);
    int tid = threadIdx.x;
    int wid = tid >> 5, lane = tid & 31;
    int band = wid & 7, half = wid >> 3;
    int b = blockIdx.y, c = blockIdx.x;

    {
        const uint4* Qh = (const uint4*)(g_Qhi + (long)b*QLEN*H);
        const uint4* Ql = (const uint4*)(g_Qlo + (long)b*QLEN*H);
        const uint4* Kh = (const uint4*)(g_Khi + (long)c*QLEN*H);
        const uint4* Kl = (const uint4*)(g_Klo + (long)c*QLEN*H);
        uint4* dQh = (uint4*)(smem + TOFF_QHI);
        uint4* dQl = (uint4*)(smem + TOFF_QLO);
        uint4* dKh = (uint4*)(smem + TOFF_KHI);
        uint4* dKl = (uint4*)(smem + TOFF_KLO);
        for (int idx=tid; idx<128*12; idx+=512) {
            int r = idx/12, q = idx%12;
            dQh[r*13+q] = Qh[idx];
            dQl[r*13+q] = Ql[idx];
            dKh[r*13+q] = Kh[idx];
            dKl[r*13+q] = Kl[idx];
        }
    }
    __syncthreads();

    // A (Q) fragments for this band
    int m0 = band*16;
    uint32_t qhi[6][4], qlo[6][4];
    {
        int rrow = m0 + (lane & 7) + ((lane >> 3) & 1) * 8;
        int rchk = ((lane >> 4) & 1) * 16;
#pragma unroll
        for (int ks=0; ks<6; ks++) {
            ldsm_x4(qhi[ks], sb + TOFF_QHI + rrow*(TRP*2) + ks*32 + rchk);
            ldsm_x4(qlo[ks], sb + TOFF_QLO + rrow*(TRP*2) + ks*32 + rchk);
        }
    }

    // GEMM: this warp's 8 n-tiles (cols [half*64, half*64+64))
    float acc[8][4];
    int brow = lane & 7;
    int bqd  = ((lane >> 3) & 3) * 16;
#pragma unroll
    for (int ntl=0; ntl<8; ntl++) {
        int gnt = half*8 + ntl;
        float a0[4]={0.f,0.f,0.f,0.f}, a1[4]={0.f,0.f,0.f,0.f};
        uint32_t bh_addr = sb + TOFF_KHI + (gnt*8+brow)*(TRP*2) + bqd;
        uint32_t bl_addr = sb + TOFF_KLO + (gnt*8+brow)*(TRP*2) + bqd;
#pragma unroll
        for (int ks2=0; ks2<3; ks2++) {
            uint32_t kh[4], kl[4];
            ldsm_x4(kh, bh_addr + ks2*64);
            ldsm_x4(kl, bl_addr + ks2*64);
            mma16816(a0, qhi[2*ks2],   kh);
            mma16816(a1, qlo[2*ks2],   kh);
            mma16816(a0, qhi[2*ks2],   kl);
            mma16816(a1, qhi[2*ks2+1], kh+2);
            mma16816(a0, qlo[2*ks2+1], kh+2);
            mma16816(a1, qhi[2*ks2+1], kl+2);
        }
#pragma unroll
        for (int i=0;i<4;i++) acc[ntl][i] = a0[i]+a1[i];
    }

    // ---- two-pass softmax across warp halves ----
    // rows: r1 = m0 + (lane>>2) (d0,d1), r2 = r1+8 (d2,d3)
    const float SC = 0.1020620726159658f;   // 1/sqrt(96)
    int r1 = m0 + (lane >> 2), r2 = r1 + 8;
    float* pm = (float*)(smem + TOFF_PM);
    float* ps = (float*)(smem + TOFF_PS);

    float m1 = -1e30f, m2 = -1e30f;
#pragma unroll
    for (int ntl=0; ntl<8; ntl++) {
        m1 = fmaxf(m1, fmaxf(acc[ntl][0], acc[ntl][1]));
        m2 = fmaxf(m2, fmaxf(acc[ntl][2], acc[ntl][3]));
    }
    m1 = fmaxf(m1, __shfl_xor_sync(0xffffffffu, m1, 1));
    m1 = fmaxf(m1, __shfl_xor_sync(0xffffffffu, m1, 2));
    m2 = fmaxf(m2, __shfl_xor_sync(0xffffffffu, m2, 1));
    m2 = fmaxf(m2, __shfl_xor_sync(0xffffffffu, m2, 2));
    if ((lane & 3) == 0) {
        pm[half*128 + r1] = m1;
        pm[half*128 + r2] = m2;
    }
    __syncthreads();
    float gm1 = fmaxf(pm[r1], pm[128 + r1]);
    float gm2 = fmaxf(pm[r2], pm[128 + r2]);

    float s1 = 0.f, s2 = 0.f;
#pragma unroll
    for (int ntl=0; ntl<8; ntl++) {
        float e0 = __expf((acc[ntl][0]-gm1)*SC);
        float e1 = __expf((acc[ntl][1]-gm1)*SC);
        float e2 = __expf((acc[ntl][2]-gm2)*SC);
        float e3 = __expf((acc[ntl][3]-gm2)*SC);
        acc[ntl][0]=e0; acc[ntl][1]=e1; acc[ntl][2]=e2; acc[ntl][3]=e3;
        s1 += e0+e1; s2 += e2+e3;
    }
    s1 += __shfl_xor_sync(0xffffffffu, s1, 1);
    s1 += __shfl_xor_sync(0xffffffffu, s1, 2);
    s2 += __shfl_xor_sync(0xffffffffu, s2, 1);
    s2 += __shfl_xor_sync(0xffffffffu, s2, 2);
    if ((lane & 3) == 0) {
        ps[half*128 + r1] = s1;
        ps[half*128 + r2] = s2;
    }
    __syncthreads();
    float inv1 = 1.f/(ps[r1] + ps[128 + r1]);
    float inv2 = 1.f/(ps[r2] + ps[128 + r2]);

    // ---- column partial sums: warp covers 64 cols of its band ----
    float* colsum = (float*)(smem + TOFF_CS);
#pragma unroll
    for (int ntl=0; ntl<8; ntl++) {
        int gnt = half*8 + ntl;
        float v0 = acc[ntl][0]*inv1 + acc[ntl][2]*inv2;
        float v1 = acc[ntl][1]*inv1 + acc[ntl][3]*inv2;
#pragma unroll
        for (int o=4; o<32; o<<=1) {
            v0 += __shfl_xor_sync(0xffffffffu, v0, o);
            v1 += __shfl_xor_sync(0xffffffffu, v1, o);
        }
        if (lane < 4) {
            colsum[band*128 + gnt*8 + lane*2]     = v0;
            colsum[band*128 + gnt*8 + lane*2 + 1] = v1;
        }
    }
    __syncthreads();

    float* wv = (float*)(smem + TOFF_WV);
    if (tid < 128) {
        float s = 0.f;
#pragma unroll
        for (int w=0; w<8; w++) s += colsum[w*128 + tid];
        wv[tid] = s * (1.f/128.f);
    }
    __syncthreads();

    float* ctxs = (float*)(smem + TOFF_CTX);
    if (tid < 96) {
        const float* Vr = g_Vt + (long)c*H*QLEN + tid*QLEN;
        float s = 0.f;
#pragma unroll
        for (int k4=0;k4<QLEN/4;k4++) {
            float4 v = ((const float4*)Vr)[k4];
            s += wv[k4*4]*v.x + wv[k4*4+1]*v.y + wv[k4*4+2]*v.z + wv[k4*4+3]*v.w;
        }
        ctxs[tid] = s;
    }
    __syncthreads();

    if (tid < 32) {
        float x0=ctxs[tid], x1=ctxs[tid+32], x2=ctxs[tid+64];
        float mu = x0+x1+x2;
#pragma unroll
        for (int o=16;o;o>>=1) mu += __shfl_xor_sync(0xffffffffu,mu,o);
        mu *= (1.f/96.f);
        float d0=x0-mu, d1=x1-mu, d2=x2-mu;
        float var = d0*d0 + d1*d1 + d2*d2;
#pragma unroll
        for (int o=16;o;o>>=1) var += __shfl_xor_sync(0xffffffffu,var,o);
        var *= (1.f/96.f);
        float rstd = rsqrtf(var + 1e-5f);
        float n0v = d0*rstd*lng[tid]    + lnb[tid];
        float n1v = d1*rstd*lng[tid+32] + lnb[tid+32];
        float n2v = d2*rstd*lng[tid+64] + lnb[tid+64];
        float ss = n0v*n0v + n1v*n1v + n2v*n2v;
#pragma unroll
        for (int o=16;o;o>>=1) ss += __shfl_xor_sync(0xffffffffu,ss,o);
        float sc = 1.f / fmaxf(sqrtf(ss), 1e-6f);
        const float* db = g_d + b*H;
        float dt = db[tid]*n0v + db[tid+32]*n1v + db[tid+64]*n2v;
#pragma unroll
        for (int o=16;o;o>>=1) dt += __shfl_xor_sync(0xffffffffu,dt,o);
        if (tid==0) out[b*64+c] += 0.5f * (dt*sc);
    }
}

// ---------------- K4: CLL via mma.sync (512 thr, 16 warps) ----------------
#define RPAD 104
#define OFF_AHI 0
#define OFF_ALO (OFF_AHI + 128*RPAD*2)
#define OFF_BHI (OFF_ALO + 128*RPAD*2)
#define OFF_BLO (OFF_BHI + 200*RPAD*2)
#define OFF_RED (OFF_BLO + 200*RPAD*2)
#define SM_CLL  (OFF_RED + 64)

__global__ __launch_bounds__(512,1) void cll_mma(float* __restrict__ out)
{
    extern __shared__ char smem[];
    uint32_t sb = smem_u32(smem);
    int tid = threadIdx.x;
    int wid = tid >> 5, lane = tid & 31;
    int band = wid & 7, half = wid >> 3;
    int b = blockIdx.y, c = blockIdx.x;

    {
        const uint4* Ah = (const uint4*)(g_Ahi + (long)b*QLEN*H);
        const uint4* Al = (const uint4*)(g_Alo + (long)b*QLEN*H);
        uint4* dAh = (uint4*)(smem + OFF_AHI);
        uint4* dAl = (uint4*)(smem + OFF_ALO);
        for (int idx=tid; idx<128*12; idx+=512) {
            int r = idx/12, q = idx%12;
            dAh[r*13+q] = Ah[idx];
            dAl[r*13+q] = Al[idx];
        }
        const uint4* Bh = (const uint4*)(g_Bhi + (long)c*PLEN*H);
        const uint4* Bl = (const uint4*)(g_Blo + (long)c*PLEN*H);
        uint4* dBh = (uint4*)(smem + OFF_BHI);
        uint4* dBl = (uint4*)(smem + OFF_BLO);
        for (int idx=tid; idx<196*12; idx+=512) {
            int r = idx/12, q = idx%12;
            dBh[r*13+q] = Bh[idx];
            dBl[r*13+q] = Bl[idx];
        }
        uint4 z = make_uint4(0,0,0,0);
        for (int idx=tid; idx<4*13; idx+=512) {
            int r = 196 + idx/13, q = idx%13;
            dBh[r*13+q] = z;
            dBl[r*13+q] = z;
        }
    }
    __syncthreads();

    int m0 = band*16;
    uint32_t ahi[6][4], alo[6][4];
    {
        int rrow = m0 + (lane & 7) + ((lane >> 3) & 1) * 8;
        int rchk = ((lane >> 4) & 1) * 16;
#pragma unroll
        for (int ks=0; ks<6; ks++) {
            ldsm_x4(ahi[ks], sb + OFF_AHI + rrow*(RPAD*2) + ks*32 + rchk);
            ldsm_x4(alo[ks], sb + OFF_ALO + rrow*(RPAD*2) + ks*32 + rchk);
        }
    }

    float mbest = -1e30f;
    int brow = lane & 7;
    int bqd  = ((lane >> 3) & 3) * 16;
    int nt0 = half ? 13 : 0;
    int nt1 = half ? 25 : 13;
    for (int nt=nt0; nt<nt1; nt++) {
        float a0[4]={0.f,0.f,0.f,0.f}, a1[4]={0.f,0.f,0.f,0.f};
        int n0 = nt*8;
        uint32_t baddr_h = sb + OFF_BHI + (n0+brow)*(RPAD*2) + bqd;
        uint32_t baddr_l = sb + OFF_BLO + (n0+brow)*(RPAD*2) + bqd;
#pragma unroll
        for (int ks2=0; ks2<3; ks2++) {
            uint32_t bh[4], bl[4];
            ldsm_x4(bh, baddr_h + ks2*64);
            ldsm_x4(bl, baddr_l + ks2*64);
            mma16816(a0, ahi[2*ks2],   bh);
            mma16816(a1, alo[2*ks2],   bh);
            mma16816(a0, ahi[2*ks2],   bl);
            mma16816(a1, ahi[2*ks2+1], bh+2);
            mma16816(a0, alo[2*ks2+1], bh+2);
            mma16816(a1, ahi[2*ks2+1], bl+2);
        }
        float v0 = a0[0]+a1[0];
        float v1 = a0[1]+a1[1];
        float v2 = a0[2]+a1[2];
        float v3 = a0[3]+a1[3];
        int col0 = n0 + (lane & 3)*2;
        if (col0 < PLEN)   mbest = fmaxf(mbest, fmaxf(v0, v2));
        if (col0+1 < PLEN) mbest = fmaxf(mbest, fmaxf(v1, v3));
    }

#pragma unroll
    for (int o=16;o;o>>=1) mbest = fmaxf(mbest, __shfl_xor_sync(0xffffffffu,mbest,o));
    float* red = (float*)(smem + OFF_RED);
    if (lane == 0) red[wid] = mbest;
    __syncthreads();
    if (tid == 0) {
        float m = red[0];
#pragma unroll
        for (int w=1;w<16;w++) m = fmaxf(m, red[w]);
        out[b*64+c] += 0.5f*m;
    }
}

// ---------------- host ----------------
extern "C" void kernel_launch(void* const* d_in, const int* in_sizes, int n_in,
                              void* d_out, int out_size)
{
    const float* z_d_cls = (const float*)d_in[0];
    const float* Z_d_tok = (const float*)d_in[1];
    const float* z_t_cls = (const float*)d_in[2];
    const float* Z_t_tok = (const float*)d_in[3];
    const float* z_v_cls = (const float*)d_in[4];
    const float* Z_v_pat = (const float*)d_in[5];
    const float *W_t_cls=(const float*)d_in[6],  *b_t_cls=(const float*)d_in[7];
    const float *W_d_cls=(const float*)d_in[8],  *b_d_cls=(const float*)d_in[9];
    const float *W_v_cls=(const float*)d_in[10], *b_v_cls=(const float*)d_in[11];
    const float *W_t_tok=(const float*)d_in[12], *b_t_tok=(const float*)d_in[13];
    const float *W_v_pat=(const float*)d_in[14], *b_v_pat=(const float*)d_in[15];
    const float *W_q=(const float*)d_in[16], *b_q=(const float*)d_in[17];
    const float *W_k=(const float*)d_in[18], *b_k=(const float*)d_in[19];
    const float *W_v=(const float*)d_in[20], *b_v=(const float*)d_in[21];
    const float *ln_g=(const float*)d_in[22], *ln_b=(const float*)d_in[23];
    float* out = (float*)d_out;

    float *Vp,*tp,*dp,*vp;
    void *qhi,*qlo,*khi,*klo,*ahi,*alo,*bhi,*blo;
    cudaGetSymbolAddress((void**)&Vp,  g_Vt);
    cudaGetSymbolAddress((void**)&tp,  g_t);
    cudaGetSymbolAddress((void**)&dp,  g_d);
    cudaGetSymbolAddress((void**)&vp,  g_v);
    cudaGetSymbolAddress(&qhi, g_Qhi);
    cudaGetSymbolAddress(&qlo, g_Qlo);
    cudaGetSymbolAddress(&khi, g_Khi);
    cudaGetSymbolAddress(&klo, g_Klo);
    cudaGetSymbolAddress(&ahi, g_Ahi);
    cudaGetSymbolAddress(&alo, g_Alo);
    cudaGetSymbolAddress(&bhi, g_Bhi);
    cudaGetSymbolAddress(&blo, g_Blo);

    cudaFuncSetAttribute(tgl_mma, cudaFuncAttributeMaxDynamicSharedMemorySize, SM_TGL);
    cudaFuncSetAttribute(cll_mma, cudaFuncAttributeMaxDynamicSharedMemorySize, SM_CLL);

    ProjArgs pa;
    for (int i=0;i<8;i++) { pa.Out2[i]=nullptr; pa.mode[i]=0; pa.L[i]=0; pa.l2n[i]=0; }
    pa.X[0]=Z_d_tok; pa.W[0]=W_q;     pa.Bv[0]=b_q;     pa.Out[0]=(float*)qhi; pa.Out2[0]=qlo; pa.mode[0]=1;
    pa.X[1]=Z_t_tok; pa.W[1]=W_k;     pa.Bv[1]=b_k;     pa.Out[1]=(float*)khi; pa.Out2[1]=klo; pa.mode[1]=1;
    pa.X[2]=Z_t_tok; pa.W[2]=W_v;     pa.Bv[2]=b_v;     pa.Out[2]=Vp;  pa.L[2]=QLEN;
    pa.X[3]=Z_t_tok; pa.W[3]=W_t_tok; pa.Bv[3]=b_t_tok; pa.Out[3]=(float*)ahi; pa.Out2[3]=alo; pa.l2n[3]=1; pa.mode[3]=1;
    pa.X[4]=Z_v_pat; pa.W[4]=W_v_pat; pa.Bv[4]=b_v_pat; pa.Out[4]=(float*)bhi; pa.Out2[4]=blo; pa.l2n[4]=1; pa.mode[4]=2;
    pa.X[5]=z_t_cls; pa.W[5]=W_t_cls; pa.Bv[5]=b_t_cls; pa.Out[5]=tp;  pa.l2n[5]=1;
    pa.X[6]=z_d_cls; pa.W[6]=W_d_cls; pa.Bv[6]=b_d_cls; pa.Out[6]=dp;  pa.l2n[6]=1;
    pa.X[7]=z_v_cls; pa.W[7]=W_v_cls; pa.Bv[7]=b_v_cls; pa.Out[7]=vp;  pa.l2n[7]=1;
    int nt[8] = {128,128,128,128,196,1,1,1};
    pa.tile_start[0]=0;
    for (int i=0;i<8;i++) pa.tile_start[i+1]=pa.tile_start[i]+nt[i];

    proj_all<<<pa.tile_start[8],256>>>(pa);

    gg_kernel<<<64,64>>>(out);
    tgl_mma<<<dim3(64,64),512,SM_TGL>>>(ln_g, ln_b, out);
    cll_mma<<<dim3(64,64),512,SM_CLL>>>(out);
}

// round 10
// speedup vs baseline: 1.2969x; 1.1674x over previous
#include <cuda_runtime.h>
#include <cuda_bf16.h>
#include <cstdint>

#define EIN 512
#define H   96
#define BSZ 64
#define QLEN 128
#define PLEN 196

// ---------------- scratch (device globals; zero-initialized) ----------------
__device__ float g_Vt [BSZ*H*QLEN];   // [c][h][q] h-major fp32
__device__ float g_t [BSZ*H];
__device__ float g_d [BSZ*H];
__device__ float g_v [BSZ*H];

// bf16 hi/lo split operands (plain row-major [b][row][h])
__device__ __nv_bfloat16 g_Qhi[BSZ*QLEN*H];
__device__ __nv_bfloat16 g_Qlo[BSZ*QLEN*H];
__device__ __nv_bfloat16 g_Khi[BSZ*QLEN*H];
__device__ __nv_bfloat16 g_Klo[BSZ*QLEN*H];
__device__ __nv_bfloat16 g_Ahi[BSZ*QLEN*H];   // t_tok
__device__ __nv_bfloat16 g_Alo[BSZ*QLEN*H];
__device__ __nv_bfloat16 g_Bhi[BSZ*PLEN*H];   // v_patch
__device__ __nv_bfloat16 g_Blo[BSZ*PLEN*H];

// ---------------- PTX helpers ----------------
__device__ __forceinline__ uint32_t smem_u32(const void* p) {
    uint32_t a;
    asm("{ .reg .u64 t; cvta.to.shared.u64 t, %1; cvt.u32.u64 %0, t; }"
        : "=r"(a) : "l"(p));
    return a;
}
__device__ __forceinline__ void ldsm_x4(uint32_t* r, uint32_t addr) {
    asm volatile("ldmatrix.sync.aligned.m8n8.x4.shared.b16 {%0,%1,%2,%3}, [%4];"
        : "=r"(r[0]),"=r"(r[1]),"=r"(r[2]),"=r"(r[3]) : "r"(addr));
}
__device__ __forceinline__ void mma16816(float* d, const uint32_t* a, const uint32_t* b) {
    asm volatile("mma.sync.aligned.m16n8k16.row.col.f32.bf16.bf16.f32 "
        "{%0,%1,%2,%3}, {%4,%5,%6,%7}, {%8,%9}, {%0,%1,%2,%3};"
        : "+f"(d[0]),"+f"(d[1]),"+f"(d[2]),"+f"(d[3])
        : "r"(a[0]),"r"(a[1]),"r"(a[2]),"r"(a[3]), "r"(b[0]),"r"(b[1]));
}

// ---------------- K1: batched projection (all 8), fused l2n / transpose / bf16-split ----------------
struct ProjArgs {
    const float* X[8];
    const float* W[8];
    const float* Bv[8];
    float*       Out[8];
    void*        Out2[8];
    int          tile_start[9];
    int          l2n[8];
    int          L[8];       // >0: fp32 transposed [row/L][96][L]
    int          mode[8];    // 0: fp32, 1: bf16 split 128 rows/b, 2: bf16 split 196 rows/c
};

__global__ __launch_bounds__(256) void proj_all(ProjArgs pa)
{
    __shared__ float Xs[64*33];
    __shared__ float Ws[96*33];

    int bid = blockIdx.x;
    int mi = 0;
#pragma unroll
    for (int i=1;i<8;i++) if (bid >= pa.tile_start[i]) mi = i;
    int tile = bid - pa.tile_start[mi];

    const float* Xb   = pa.X[mi] + (long)tile*64*EIN;
    const float* W    = pa.W[mi];
    const float* bias = pa.Bv[mi];

    int tid = threadIdx.x;
    int tm = tid >> 4, tn = tid & 15;
    int m0 = tm*4,  n0 = tn*6;

    float acc[4][6];
#pragma unroll
    for (int i=0;i<4;i++)
#pragma unroll
        for (int j=0;j<6;j++) acc[i][j]=0.f;

    for (int k0=0;k0<EIN;k0+=32) {
        __syncthreads();
        for (int idx=tid; idx<64*32; idx+=256) {
            int m = idx>>5, kk = idx&31;
            Xs[m*33+kk] = Xb[m*EIN + k0 + kk];
        }
        for (int idx=tid; idx<96*32; idx+=256) {
            int n = idx>>5, kk = idx&31;
            Ws[n*33+kk] = W[n*EIN + k0 + kk];
        }
        __syncthreads();
#pragma unroll 8
        for (int kk=0;kk<32;kk++) {
            float a[4], b[6];
#pragma unroll
            for (int i=0;i<4;i++) a[i]=Xs[(m0+i)*33+kk];
#pragma unroll
            for (int j=0;j<6;j++) b[j]=Ws[(n0+j)*33+kk];
#pragma unroll
            for (int i=0;i<4;i++)
#pragma unroll
                for (int j=0;j<6;j++) acc[i][j] += a[i]*b[j];
        }
    }

#pragma unroll
    for (int i=0;i<4;i++)
#pragma unroll
        for (int j=0;j<6;j++) acc[i][j] += bias[n0+j];

    if (pa.l2n[mi]) {
        __syncthreads();
#pragma unroll
        for (int i=0;i<4;i++) {
            float ss = 0.f;
#pragma unroll
            for (int j=0;j<6;j++) ss += acc[i][j]*acc[i][j];
            Xs[(m0+i)*17 + tn] = ss;
        }
        __syncthreads();
        if (tid < 64) {
            float s = 0.f;
#pragma unroll
            for (int t=0;t<16;t++) s += Xs[tid*17+t];
            Ws[tid] = 1.f / fmaxf(sqrtf(s), 1e-6f);
        }
        __syncthreads();
#pragma unroll
        for (int i=0;i<4;i++) {
            float sc = Ws[m0+i];
#pragma unroll
            for (int j=0;j<6;j++) acc[i][j] *= sc;
        }
    }

    int mode = pa.mode[mi];
    if (mode) {
        int perlen = (mode==1) ? 128 : 196;
        __nv_bfloat16* hiB = (__nv_bfloat16*)pa.Out[mi];
        __nv_bfloat16* loB = (__nv_bfloat16*)pa.Out2[mi];
#pragma unroll
        for (int i=0;i<4;i++) {
            int gr = tile*64 + m0 + i;
            int bb = gr / perlen, rr = gr - bb*perlen;
            long base = ((long)bb*perlen + rr)*H + n0;
#pragma unroll
            for (int j=0;j<6;j++) {
                float x = acc[i][j];
                __nv_bfloat16 hv = __float2bfloat16(x);
                __nv_bfloat16 lv = __float2bfloat16(x - __bfloat162float(hv));
                hiB[base+j] = hv;
                loB[base+j] = lv;
            }
        }
    } else {
        int L = pa.L[mi];
        if (L > 0) {
            float* O = pa.Out[mi];
#pragma unroll
            for (int i=0;i<4;i++) {
                int gr = tile*64 + m0 + i;
                int bb = gr / L, pp = gr - bb*L;
                float* base = O + (long)bb*H*L + pp;
#pragma unroll
                for (int j=0;j<6;j++) base[(n0+j)*L] = acc[i][j];
            }
        } else {
            float* O = pa.Out[mi] + (long)tile*64*H;
#pragma unroll
            for (int i=0;i<4;i++)
#pragma unroll
                for (int j=0;j<6;j++) O[(m0+i)*H + n0 + j] = acc[i][j];
        }
    }
}

// ---------------- K3: TGL via mma.sync (256 thr, 8 warps, k-outer, gg folded) ----------------
#define TRP 104
#define TOFF_QHI 0
#define TOFF_QLO (TOFF_QHI + 128*TRP*2)
#define TOFF_KHI (TOFF_QLO + 128*TRP*2)
#define TOFF_KLO (TOFF_KHI + 128*TRP*2)
#define TOFF_CS  (TOFF_KLO + 128*TRP*2)      // [8][128] f32 colsum per band
#define TOFF_WV  (TOFF_CS + 8*128*4)         // [128] f32
#define TOFF_CTX (TOFF_WV + 128*4)           // [96] f32
#define SM_TGL   (TOFF_CTX + 96*4 + 16)      // ~111.5 KB

__global__ __launch_bounds__(256,2) void tgl_mma(
    const float* __restrict__ lng, const float* __restrict__ lnb,
    float* __restrict__ out)
{
    extern __shared__ char smem[];
    uint32_t sb = smem_u32(smem);
    int tid = threadIdx.x;
    int wid = tid >> 5, lane = tid & 31;
    int b = blockIdx.y, c = blockIdx.x;

    {
        const uint4* Qh = (const uint4*)(g_Qhi + (long)b*QLEN*H);
        const uint4* Ql = (const uint4*)(g_Qlo + (long)b*QLEN*H);
        const uint4* Kh = (const uint4*)(g_Khi + (long)c*QLEN*H);
        const uint4* Kl = (const uint4*)(g_Klo + (long)c*QLEN*H);
        uint4* dQh = (uint4*)(smem + TOFF_QHI);
        uint4* dQl = (uint4*)(smem + TOFF_QLO);
        uint4* dKh = (uint4*)(smem + TOFF_KHI);
        uint4* dKl = (uint4*)(smem + TOFF_KLO);
        for (int idx=tid; idx<128*12; idx+=256) {
            int r = idx/12, q = idx%12;
            dQh[r*13+q] = Qh[idx];
            dQl[r*13+q] = Ql[idx];
            dKh[r*13+q] = Kh[idx];
            dKl[r*13+q] = Kl[idx];
        }
    }
    __syncthreads();

    int m0 = wid*16;
    float acc[16][4];
#pragma unroll
    for (int nt=0;nt<16;nt++)
#pragma unroll
        for (int i=0;i<4;i++) acc[nt][i]=0.f;

    int rrow = m0 + (lane & 7) + ((lane >> 3) & 1) * 8;
    int rchk = ((lane >> 4) & 1) * 16;
    int brow = lane & 7;
    int bqd  = ((lane >> 3) & 3) * 16;

    // k-outer: 3 chunks of 32 k; A frags 16 regs at a time
#pragma unroll
    for (int kc=0; kc<3; kc++) {
        uint32_t qh0[4], qh1[4], ql0[4], ql1[4];
        uint32_t abase = rrow*(TRP*2) + kc*64 + rchk;
        ldsm_x4(qh0, sb + TOFF_QHI + abase);
        ldsm_x4(qh1, sb + TOFF_QHI + abase + 32);
        ldsm_x4(ql0, sb + TOFF_QLO + abase);
        ldsm_x4(ql1, sb + TOFF_QLO + abase + 32);
#pragma unroll
        for (int nt=0; nt<16; nt++) {
            uint32_t kh[4], kl[4];
            uint32_t bbase = (nt*8+brow)*(TRP*2) + bqd + kc*64;
            ldsm_x4(kh, sb + TOFF_KHI + bbase);
            ldsm_x4(kl, sb + TOFF_KLO + bbase);
            mma16816(acc[nt], qh0, kh);
            mma16816(acc[nt], ql0, kh);
            mma16816(acc[nt], qh0, kl);
            mma16816(acc[nt], qh1, kh+2);
            mma16816(acc[nt], ql1, kh+2);
            mma16816(acc[nt], qh1, kl+2);
        }
    }

    // single-pass in-warp row softmax (full rows in warp)
    const float SC = 0.1020620726159658f;   // 1/sqrt(96)
    float m1 = -1e30f, m2 = -1e30f;
#pragma unroll
    for (int nt=0; nt<16; nt++) {
        m1 = fmaxf(m1, fmaxf(acc[nt][0], acc[nt][1]));
        m2 = fmaxf(m2, fmaxf(acc[nt][2], acc[nt][3]));
    }
    m1 = fmaxf(m1, __shfl_xor_sync(0xffffffffu, m1, 1));
    m1 = fmaxf(m1, __shfl_xor_sync(0xffffffffu, m1, 2));
    m2 = fmaxf(m2, __shfl_xor_sync(0xffffffffu, m2, 1));
    m2 = fmaxf(m2, __shfl_xor_sync(0xffffffffu, m2, 2));

    float s1 = 0.f, s2 = 0.f;
#pragma unroll
    for (int nt=0; nt<16; nt++) {
        float e0 = __expf((acc[nt][0]-m1)*SC);
        float e1 = __expf((acc[nt][1]-m1)*SC);
        float e2 = __expf((acc[nt][2]-m2)*SC);
        float e3 = __expf((acc[nt][3]-m2)*SC);
        acc[nt][0]=e0; acc[nt][1]=e1; acc[nt][2]=e2; acc[nt][3]=e3;
        s1 += e0+e1; s2 += e2+e3;
    }
    s1 += __shfl_xor_sync(0xffffffffu, s1, 1);
    s1 += __shfl_xor_sync(0xffffffffu, s1, 2);
    s2 += __shfl_xor_sync(0xffffffffu, s2, 1);
    s2 += __shfl_xor_sync(0xffffffffu, s2, 2);
    float inv1 = 1.f/s1, inv2 = 1.f/s2;

    float* colsum = (float*)(smem + TOFF_CS);
#pragma unroll
    for (int nt=0; nt<16; nt++) {
        float v0 = acc[nt][0]*inv1 + acc[nt][2]*inv2;
        float v1 = acc[nt][1]*inv1 + acc[nt][3]*inv2;
#pragma unroll
        for (int o=4; o<32; o<<=1) {
            v0 += __shfl_xor_sync(0xffffffffu, v0, o);
            v1 += __shfl_xor_sync(0xffffffffu, v1, o);
        }
        if (lane < 4) {
            colsum[wid*128 + nt*8 + lane*2]     = v0;
            colsum[wid*128 + nt*8 + lane*2 + 1] = v1;
        }
    }
    __syncthreads();

    float* wv = (float*)(smem + TOFF_WV);
    if (tid < 128) {
        float s = 0.f;
#pragma unroll
        for (int w=0; w<8; w++) s += colsum[w*128 + tid];
        wv[tid] = s * (1.f/128.f);
    }
    __syncthreads();

    float* ctxs = (float*)(smem + TOFF_CTX);
    if (tid < 96) {
        const float* Vr = g_Vt + (long)c*H*QLEN + tid*QLEN;
        float s = 0.f;
#pragma unroll
        for (int k4=0;k4<QLEN/4;k4++) {
            float4 v = ((const float4*)Vr)[k4];
            s += wv[k4*4]*v.x + wv[k4*4+1]*v.y + wv[k4*4+2]*v.z + wv[k4*4+3]*v.w;
        }
        ctxs[tid] = s;
    }
    __syncthreads();

    // LayerNorm + l2n + dot(d[b]) + folded gg term; single "=" write
    if (tid < 32) {
        float x0=ctxs[tid], x1=ctxs[tid+32], x2=ctxs[tid+64];
        float mu = x0+x1+x2;
#pragma unroll
        for (int o=16;o;o>>=1) mu += __shfl_xor_sync(0xffffffffu,mu,o);
        mu *= (1.f/96.f);
        float d0=x0-mu, d1=x1-mu, d2=x2-mu;
        float var = d0*d0 + d1*d1 + d2*d2;
#pragma unroll
        for (int o=16;o;o>>=1) var += __shfl_xor_sync(0xffffffffu,var,o);
        var *= (1.f/96.f);
        float rstd = rsqrtf(var + 1e-5f);
        float n0v = d0*rstd*lng[tid]    + lnb[tid];
        float n1v = d1*rstd*lng[tid+32] + lnb[tid+32];
        float n2v = d2*rstd*lng[tid+64] + lnb[tid+64];
        float ss = n0v*n0v + n1v*n1v + n2v*n2v;
#pragma unroll
        for (int o=16;o;o>>=1) ss += __shfl_xor_sync(0xffffffffu,ss,o);
        float sc = 1.f / fmaxf(sqrtf(ss), 1e-6f);
        const float* db = g_d + b*H;   // tgl uses d[b]
        const float* tb = g_t + b*H;   // gg uses t[b]
        const float* dc = g_d + c*H;   // gg uses d[c]
        const float* vc = g_v + c*H;   // gg uses v[c]
        float part = (db[tid]*n0v + db[tid+32]*n1v + db[tid+64]*n2v)*sc
                   + tb[tid]   *(dc[tid]   +vc[tid])
                   + tb[tid+32]*(dc[tid+32]+vc[tid+32])
                   + tb[tid+64]*(dc[tid+64]+vc[tid+64]);
#pragma unroll
        for (int o=16;o;o>>=1) part += __shfl_xor_sync(0xffffffffu,part,o);
        if (tid==0) out[b*64+c] = 0.5f * part;
    }
}

// ---------------- K4: CLL via mma.sync (256 thr, 8 warps, chunked B) ----------------
#define RPAD 104
#define COFF_AHI 0
#define COFF_ALO (COFF_AHI + 128*RPAD*2)
#define COFF_BHI (COFF_ALO + 128*RPAD*2)       // chunk buffer: 104 rows
#define COFF_BLO (COFF_BHI + 104*RPAD*2)
#define COFF_RED (COFF_BLO + 104*RPAD*2)
#define SM_CLL  (COFF_RED + 64)                // ~96.6 KB

__global__ __launch_bounds__(256,2) void cll_mma(float* __restrict__ out)
{
    extern __shared__ char smem[];
    uint32_t sb = smem_u32(smem);
    int tid = threadIdx.x;
    int wid = tid >> 5, lane = tid & 31;
    int b = blockIdx.y, c = blockIdx.x;

    const uint4* Bh = (const uint4*)(g_Bhi + (long)c*PLEN*H);
    const uint4* Bl = (const uint4*)(g_Blo + (long)c*PLEN*H);
    uint4* dBh = (uint4*)(smem + COFF_BHI);
    uint4* dBl = (uint4*)(smem + COFF_BLO);

    // load A full + B chunk0 (rows 0..103)
    {
        const uint4* Ah = (const uint4*)(g_Ahi + (long)b*QLEN*H);
        const uint4* Al = (const uint4*)(g_Alo + (long)b*QLEN*H);
        uint4* dAh = (uint4*)(smem + COFF_AHI);
        uint4* dAl = (uint4*)(smem + COFF_ALO);
        for (int idx=tid; idx<128*12; idx+=256) {
            int r = idx/12, q = idx%12;
            dAh[r*13+q] = Ah[idx];
            dAl[r*13+q] = Al[idx];
        }
        for (int idx=tid; idx<104*12; idx+=256) {
            int r = idx/12, q = idx%12;
            dBh[r*13+q] = Bh[idx];
            dBl[r*13+q] = Bl[idx];
        }
    }
    __syncthreads();

    // A fragments (resident across both chunks)
    int m0 = wid*16;
    uint32_t ahi[6][4], alo[6][4];
    {
        int rrow = m0 + (lane & 7) + ((lane >> 3) & 1) * 8;
        int rchk = ((lane >> 4) & 1) * 16;
#pragma unroll
        for (int ks=0; ks<6; ks++) {
            ldsm_x4(ahi[ks], sb + COFF_AHI + rrow*(RPAD*2) + ks*32 + rchk);
            ldsm_x4(alo[ks], sb + COFF_ALO + rrow*(RPAD*2) + ks*32 + rchk);
        }
    }

    float mbest = -1e30f;
    int brow = lane & 7;
    int bqd  = ((lane >> 3) & 3) * 16;

    // ---- chunk 0: nt 0..12 (cols 0..103, all valid) ----
    for (int nt=0; nt<13; nt++) {
        float a0[4]={0.f,0.f,0.f,0.f}, a1[4]={0.f,0.f,0.f,0.f};
        uint32_t baddr_h = sb + COFF_BHI + (nt*8+brow)*(RPAD*2) + bqd;
        uint32_t baddr_l = sb + COFF_BLO + (nt*8+brow)*(RPAD*2) + bqd;
#pragma unroll
        for (int ks2=0; ks2<3; ks2++) {
            uint32_t bh[4], bl[4];
            ldsm_x4(bh, baddr_h + ks2*64);
            ldsm_x4(bl, baddr_l + ks2*64);
            mma16816(a0, ahi[2*ks2],   bh);
            mma16816(a1, alo[2*ks2],   bh);
            mma16816(a0, ahi[2*ks2],   bl);
            mma16816(a1, ahi[2*ks2+1], bh+2);
            mma16816(a0, alo[2*ks2+1], bh+2);
            mma16816(a1, ahi[2*ks2+1], bl+2);
        }
        mbest = fmaxf(mbest, fmaxf(fmaxf(a0[0]+a1[0], a0[1]+a1[1]),
                                   fmaxf(a0[2]+a1[2], a0[3]+a1[3])));
    }

    __syncthreads();   // all warps done reading chunk0

    // load chunk1 (global rows 104..195 -> local 0..91; local 92..95 zero)
    for (int idx=tid; idx<92*12; idx+=256) {
        int r = idx/12, q = idx%12;
        dBh[r*13+q] = Bh[(104+r)*12+q];
        dBl[r*13+q] = Bl[(104+r)*12+q];
    }
    {
        uint4 z = make_uint4(0,0,0,0);
        for (int idx=tid; idx<4*13; idx+=256) {
            int r = 92 + idx/13, q = idx%13;
            dBh[r*13+q] = z;
            dBl[r*13+q] = z;
        }
    }
    __syncthreads();

    // ---- chunk 1: nt 13..24 (global cols 104..199; mask >=196) ----
    for (int nt=13; nt<25; nt++) {
        float a0[4]={0.f,0.f,0.f,0.f}, a1[4]={0.f,0.f,0.f,0.f};
        int ln0 = nt*8 - 104;
        uint32_t baddr_h = sb + COFF_BHI + (ln0+brow)*(RPAD*2) + bqd;
        uint32_t baddr_l = sb + COFF_BLO + (ln0+brow)*(RPAD*2) + bqd;
#pragma unroll
        for (int ks2=0; ks2<3; ks2++) {
            uint32_t bh[4], bl[4];
            ldsm_x4(bh, baddr_h + ks2*64);
            ldsm_x4(bl, baddr_l + ks2*64);
            mma16816(a0, ahi[2*ks2],   bh);
            mma16816(a1, alo[2*ks2],   bh);
            mma16816(a0, ahi[2*ks2],   bl);
            mma16816(a1, ahi[2*ks2+1], bh+2);
            mma16816(a0, alo[2*ks2+1], bh+2);
            mma16816(a1, ahi[2*ks2+1], bl+2);
        }
        int col0 = nt*8 + (lane & 3)*2;
        if (col0 < PLEN)   mbest = fmaxf(mbest, fmaxf(a0[0]+a1[0], a0[2]+a1[2]));
        if (col0+1 < PLEN) mbest = fmaxf(mbest, fmaxf(a0[1]+a1[1], a0[3]+a1[3]));
    }

#pragma unroll
    for (int o=16;o;o>>=1) mbest = fmaxf(mbest, __shfl_xor_sync(0xffffffffu,mbest,o));
    float* red = (float*)(smem + COFF_RED);
    if (lane == 0) red[wid] = mbest;
    __syncthreads();
    if (tid == 0) {
        float m = red[0];
#pragma unroll
        for (int w=1;w<8;w++) m = fmaxf(m, red[w]);
        out[b*64+c] += 0.5f*m;
    }
}

// ---------------- host ----------------
extern "C" void kernel_launch(void* const* d_in, const int* in_sizes, int n_in,
                              void* d_out, int out_size)
{
    const float* z_d_cls = (const float*)d_in[0];
    const float* Z_d_tok = (const float*)d_in[1];
    const float* z_t_cls = (const float*)d_in[2];
    const float* Z_t_tok = (const float*)d_in[3];
    const float* z_v_cls = (const float*)d_in[4];
    const float* Z_v_pat = (const float*)d_in[5];
    const float *W_t_cls=(const float*)d_in[6],  *b_t_cls=(const float*)d_in[7];
    const float *W_d_cls=(const float*)d_in[8],  *b_d_cls=(const float*)d_in[9];
    const float *W_v_cls=(const float*)d_in[10], *b_v_cls=(const float*)d_in[11];
    const float *W_t_tok=(const float*)d_in[12], *b_t_tok=(const float*)d_in[13];
    const float *W_v_pat=(const float*)d_in[14], *b_v_pat=(const float*)d_in[15];
    const float *W_q=(const float*)d_in[16], *b_q=(const float*)d_in[17];
    const float *W_k=(const float*)d_in[18], *b_k=(const float*)d_in[19];
    const float *W_v=(const float*)d_in[20], *b_v=(const float*)d_in[21];
    const float *ln_g=(const float*)d_in[22], *ln_b=(const float*)d_in[23];
    float* out = (float*)d_out;

    float *Vp,*tp,*dp,*vp;
    void *qhi,*qlo,*khi,*klo,*ahi,*alo,*bhi,*blo;
    cudaGetSymbolAddress((void**)&Vp,  g_Vt);
    cudaGetSymbolAddress((void**)&tp,  g_t);
    cudaGetSymbolAddress((void**)&dp,  g_d);
    cudaGetSymbolAddress((void**)&vp,  g_v);
    cudaGetSymbolAddress(&qhi, g_Qhi);
    cudaGetSymbolAddress(&qlo, g_Qlo);
    cudaGetSymbolAddress(&khi, g_Khi);
    cudaGetSymbolAddress(&klo, g_Klo);
    cudaGetSymbolAddress(&ahi, g_Ahi);
    cudaGetSymbolAddress(&alo, g_Alo);
    cudaGetSymbolAddress(&bhi, g_Bhi);
    cudaGetSymbolAddress(&blo, g_Blo);

    cudaFuncSetAttribute(tgl_mma, cudaFuncAttributeMaxDynamicSharedMemorySize, SM_TGL);
    cudaFuncSetAttribute(cll_mma, cudaFuncAttributeMaxDynamicSharedMemorySize, SM_CLL);

    ProjArgs pa;
    for (int i=0;i<8;i++) { pa.Out2[i]=nullptr; pa.mode[i]=0; pa.L[i]=0; pa.l2n[i]=0; }
    pa.X[0]=Z_d_tok; pa.W[0]=W_q;     pa.Bv[0]=b_q;     pa.Out[0]=(float*)qhi; pa.Out2[0]=qlo; pa.mode[0]=1;
    pa.X[1]=Z_t_tok; pa.W[1]=W_k;     pa.Bv[1]=b_k;     pa.Out[1]=(float*)khi; pa.Out2[1]=klo; pa.mode[1]=1;
    pa.X[2]=Z_t_tok; pa.W[2]=W_v;     pa.Bv[2]=b_v;     pa.Out[2]=Vp;  pa.L[2]=QLEN;
    pa.X[3]=Z_t_tok; pa.W[3]=W_t_tok; pa.Bv[3]=b_t_tok; pa.Out[3]=(float*)ahi; pa.Out2[3]=alo; pa.l2n[3]=1; pa.mode[3]=1;
    pa.X[4]=Z_v_pat; pa.W[4]=W_v_pat; pa.Bv[4]=b_v_pat; pa.Out[4]=(float*)bhi; pa.Out2[4]=blo; pa.l2n[4]=1; pa.mode[4]=2;
    pa.X[5]=z_t_cls; pa.W[5]=W_t_cls; pa.Bv[5]=b_t_cls; pa.Out[5]=tp;  pa.l2n[5]=1;
    pa.X[6]=z_d_cls; pa.W[6]=W_d_cls; pa.Bv[6]=b_d_cls; pa.Out[6]=dp;  pa.l2n[6]=1;
    pa.X[7]=z_v_cls; pa.W[7]=W_v_cls; pa.Bv[7]=b_v_cls; pa.Out[7]=vp;  pa.l2n[7]=1;
    int nt[8] = {128,128,128,128,196,1,1,1};
    pa.tile_start[0]=0;
    for (int i=0;i<8;i++) pa.tile_start[i+1]=pa.tile_start[i]+nt[i];

    proj_all<<<pa.tile_start[8],256>>>(pa);

    // out = 0.5*(S_TGG + S_CGG + S_TGL)   (gg folded into tgl epilogue, "=" write)
    tgl_mma<<<dim3(64,64),256,SM_TGL>>>(ln_g, ln_b, out);
    // out += 0.5*S_CLL
    cll_mma<<<dim3(64,64),256,SM_CLL>>>(out);
}

// round 11
// speedup vs baseline: 1.6095x; 1.2411x over previous
#include <cuda_runtime.h>
#include <cuda_bf16.h>
#include <cstdint>

#define EIN 512
#define H   96
#define BSZ 64
#define QLEN 128
#define PLEN 196

// ---------------- scratch (device globals; zero-initialized) ----------------
__device__ float g_Vt [BSZ*H*QLEN];   // [c][h][q] h-major fp32
__device__ float g_t [BSZ*H];
__device__ float g_d [BSZ*H];
__device__ float g_v [BSZ*H];

// bf16 hi/lo split operands (plain row-major [b][row][h])
__device__ __nv_bfloat16 g_Qhi[BSZ*QLEN*H];
__device__ __nv_bfloat16 g_Qlo[BSZ*QLEN*H];
__device__ __nv_bfloat16 g_Khi[BSZ*QLEN*H];
__device__ __nv_bfloat16 g_Klo[BSZ*QLEN*H];
__device__ __nv_bfloat16 g_Ahi[BSZ*QLEN*H];   // t_tok
__device__ __nv_bfloat16 g_Alo[BSZ*QLEN*H];
__device__ __nv_bfloat16 g_Bhi[BSZ*PLEN*H];   // v_patch
__device__ __nv_bfloat16 g_Blo[BSZ*PLEN*H];

// ---------------- PTX helpers ----------------
__device__ __forceinline__ uint32_t smem_u32(const void* p) {
    uint32_t a;
    asm("{ .reg .u64 t; cvta.to.shared.u64 t, %1; cvt.u32.u64 %0, t; }"
        : "=r"(a) : "l"(p));
    return a;
}
__device__ __forceinline__ void ldsm_x4(uint32_t* r, uint32_t addr) {
    asm volatile("ldmatrix.sync.aligned.m8n8.x4.shared.b16 {%0,%1,%2,%3}, [%4];"
        : "=r"(r[0]),"=r"(r[1]),"=r"(r[2]),"=r"(r[3]) : "r"(addr));
}
__device__ __forceinline__ void mma16816(float* d, const uint32_t* a, const uint32_t* b) {
    asm volatile("mma.sync.aligned.m16n8k16.row.col.f32.bf16.bf16.f32 "
        "{%0,%1,%2,%3}, {%4,%5,%6,%7}, {%8,%9}, {%0,%1,%2,%3};"
        : "+f"(d[0]),"+f"(d[1]),"+f"(d[2]),"+f"(d[3])
        : "r"(a[0]),"r"(a[1]),"r"(a[2]),"r"(a[3]), "r"(b[0]),"r"(b[1]));
}
__device__ __forceinline__ uint32_t pack_hi2(float x, float y) {
    __nv_bfloat162 h = __floats2bfloat162_rn(x, y);
    return *(uint32_t*)&h;
}

// ---------------- K1: batched projection via mma.sync split-bf16 ----------------
struct ProjArgs {
    const float* X[8];
    const float* W[8];
    const float* Bv[8];
    float*       Out[8];
    void*        Out2[8];
    int          tile_start[9];
    int          l2n[8];
    int          L[8];       // >0 (mode 0): fp32 transposed [row/L][96][L]
    int          mode[8];    // 0: fp32, 1: bf16 split 128 rows/b, 2: bf16 split 196 rows/c
};

#define PRP  136                                 // padded row: 136 bf16 = 272 B
#define POFF_XHI 0
#define POFF_XLO (POFF_XHI + 64*PRP*2)
#define POFF_WHI (POFF_XLO + 64*PRP*2)
#define POFF_WLO (POFF_WHI + 96*PRP*2)
#define POFF_RED (POFF_WLO + 96*PRP*2)           // [64][2] f32 partial ss
#define SM_PROJ  (POFF_RED + 64*2*4 + 16)        // ~87.6 KB

__global__ __launch_bounds__(256,2) void proj_mma(ProjArgs pa)
{
    extern __shared__ char smem[];
    uint32_t sb = smem_u32(smem);
    int tid = threadIdx.x;
    int wid = tid >> 5, lane = tid & 31;
    int band = wid & 3, nhalf = wid >> 2;

    int bid = blockIdx.x;
    int mi = 0;
#pragma unroll
    for (int i=1;i<8;i++) if (bid >= pa.tile_start[i]) mi = i;
    int tile = bid - pa.tile_start[mi];

    const float* Xb = pa.X[mi] + (long)tile*64*EIN;
    const float* W  = pa.W[mi];

    float acc[6][4];
#pragma unroll
    for (int nt=0;nt<6;nt++)
#pragma unroll
        for (int i=0;i<4;i++) acc[nt][i]=0.f;

    int rrow = band*16 + (lane & 7) + ((lane >> 3) & 1) * 8;
    int rchk = ((lane >> 4) & 1) * 16;
    int brow = lane & 7;
    int bqd  = ((lane >> 3) & 3) * 16;

    for (int kc=0; kc<4; kc++) {
        __syncthreads();
        // X chunk: 64 rows x 128 k, fp32 -> bf16 hi/lo during store
        for (int idx=tid; idx<64*32; idx+=256) {
            int r = idx>>5, k4 = idx&31;
            float4 x = *(const float4*)(Xb + r*EIN + kc*128 + k4*4);
            __nv_bfloat16 h0=__float2bfloat16(x.x), h1=__float2bfloat16(x.y),
                          h2=__float2bfloat16(x.z), h3=__float2bfloat16(x.w);
            uint2 hw, lw;
            hw.x = pack_hi2(x.x, x.y); hw.y = pack_hi2(x.z, x.w);
            lw.x = pack_hi2(x.x-__bfloat162float(h0), x.y-__bfloat162float(h1));
            lw.y = pack_hi2(x.z-__bfloat162float(h2), x.w-__bfloat162float(h3));
            *(uint2*)(smem + POFF_XHI + r*(PRP*2) + k4*8) = hw;
            *(uint2*)(smem + POFF_XLO + r*(PRP*2) + k4*8) = lw;
        }
        // W chunk: 96 rows x 128 k
        for (int idx=tid; idx<96*32; idx+=256) {
            int r = idx>>5, k4 = idx&31;
            float4 x = *(const float4*)(W + r*EIN + kc*128 + k4*4);
            __nv_bfloat16 h0=__float2bfloat16(x.x), h1=__float2bfloat16(x.y),
                          h2=__float2bfloat16(x.z), h3=__float2bfloat16(x.w);
            uint2 hw, lw;
            hw.x = pack_hi2(x.x, x.y); hw.y = pack_hi2(x.z, x.w);
            lw.x = pack_hi2(x.x-__bfloat162float(h0), x.y-__bfloat162float(h1));
            lw.y = pack_hi2(x.z-__bfloat162float(h2), x.w-__bfloat162float(h3));
            *(uint2*)(smem + POFF_WHI + r*(PRP*2) + k4*8) = hw;
            *(uint2*)(smem + POFF_WLO + r*(PRP*2) + k4*8) = lw;
        }
        __syncthreads();

#pragma unroll
        for (int ks2=0; ks2<4; ks2++) {
            uint32_t xh0[4], xh1[4], xl0[4], xl1[4];
            uint32_t abase = rrow*(PRP*2) + ks2*64 + rchk;
            ldsm_x4(xh0, sb + POFF_XHI + abase);
            ldsm_x4(xh1, sb + POFF_XHI + abase + 32);
            ldsm_x4(xl0, sb + POFF_XLO + abase);
            ldsm_x4(xl1, sb + POFF_XLO + abase + 32);
#pragma unroll
            for (int nt=0; nt<6; nt++) {
                uint32_t wh[4], wl[4];
                uint32_t bbase = (nhalf*48+nt*8+brow)*(PRP*2) + bqd + ks2*64;
                ldsm_x4(wh, sb + POFF_WHI + bbase);
                ldsm_x4(wl, sb + POFF_WLO + bbase);
                mma16816(acc[nt], xh0, wh);
                mma16816(acc[nt], xl0, wh);
                mma16816(acc[nt], xh0, wl);
                mma16816(acc[nt], xh1, wh+2);
                mma16816(acc[nt], xl1, wh+2);
                mma16816(acc[nt], xh1, wl+2);
            }
        }
    }

    // ---- epilogue: bias, optional l2n, mode-dispatched writes ----
    int r1 = band*16 + (lane >> 2), r2 = r1 + 8;
    const float* bias = pa.Bv[mi];
#pragma unroll
    for (int nt=0; nt<6; nt++) {
        int c0 = nhalf*48 + nt*8 + (lane & 3)*2;
        float b0 = bias[c0], b1 = bias[c0+1];
        acc[nt][0] += b0; acc[nt][1] += b1;
        acc[nt][2] += b0; acc[nt][3] += b1;
    }

    if (pa.l2n[mi]) {
        float ss1 = 0.f, ss2 = 0.f;
#pragma unroll
        for (int nt=0; nt<6; nt++) {
            ss1 += acc[nt][0]*acc[nt][0] + acc[nt][1]*acc[nt][1];
            ss2 += acc[nt][2]*acc[nt][2] + acc[nt][3]*acc[nt][3];
        }
        ss1 += __shfl_xor_sync(0xffffffffu, ss1, 1);
        ss1 += __shfl_xor_sync(0xffffffffu, ss1, 2);
        ss2 += __shfl_xor_sync(0xffffffffu, ss2, 1);
        ss2 += __shfl_xor_sync(0xffffffffu, ss2, 2);
        float* red = (float*)(smem + POFF_RED);
        __syncthreads();   // smem X/W reads done before reuse
        if ((lane & 3) == 0) {
            red[r1*2 + nhalf] = ss1;
            red[r2*2 + nhalf] = ss2;
        }
        __syncthreads();
        float sc1 = 1.f / fmaxf(sqrtf(red[r1*2] + red[r1*2+1]), 1e-6f);
        float sc2 = 1.f / fmaxf(sqrtf(red[r2*2] + red[r2*2+1]), 1e-6f);
#pragma unroll
        for (int nt=0; nt<6; nt++) {
            acc[nt][0] *= sc1; acc[nt][1] *= sc1;
            acc[nt][2] *= sc2; acc[nt][3] *= sc2;
        }
    }

    int mode = pa.mode[mi];
    int gr1 = tile*64 + r1, gr2 = tile*64 + r2;
    if (mode) {
        int perlen = (mode==1) ? 128 : 196;
        __nv_bfloat16* hiB = (__nv_bfloat16*)pa.Out[mi];
        __nv_bfloat16* loB = (__nv_bfloat16*)pa.Out2[mi];
        int bb1 = gr1/perlen, rr1 = gr1 - bb1*perlen;
        int bb2 = gr2/perlen, rr2 = gr2 - bb2*perlen;
        long base1 = ((long)bb1*perlen + rr1)*H;
        long base2 = ((long)bb2*perlen + rr2)*H;
#pragma unroll
        for (int nt=0; nt<6; nt++) {
            int c0 = nhalf*48 + nt*8 + (lane & 3)*2;
#pragma unroll
            for (int j=0;j<2;j++) {
                float v1 = acc[nt][j], v2 = acc[nt][2+j];
                __nv_bfloat16 h1v = __float2bfloat16(v1);
                __nv_bfloat16 h2v = __float2bfloat16(v2);
                hiB[base1 + c0 + j] = h1v;
                loB[base1 + c0 + j] = __float2bfloat16(v1 - __bfloat162float(h1v));
                hiB[base2 + c0 + j] = h2v;
                loB[base2 + c0 + j] = __float2bfloat16(v2 - __bfloat162float(h2v));
            }
        }
    } else if (pa.L[mi] > 0) {
        int L = pa.L[mi];
        float* O = pa.Out[mi];
        int bb1 = gr1/L, pp1 = gr1 - bb1*L;
        int bb2 = gr2/L, pp2 = gr2 - bb2*L;
#pragma unroll
        for (int nt=0; nt<6; nt++) {
            int c0 = nhalf*48 + nt*8 + (lane & 3)*2;
#pragma unroll
            for (int j=0;j<2;j++) {
                O[((long)bb1*H + c0 + j)*L + pp1] = acc[nt][j];
                O[((long)bb2*H + c0 + j)*L + pp2] = acc[nt][2+j];
            }
        }
    } else {
        float* O = pa.Out[mi];
#pragma unroll
        for (int nt=0; nt<6; nt++) {
            int c0 = nhalf*48 + nt*8 + (lane & 3)*2;
#pragma unroll
            for (int j=0;j<2;j++) {
                O[(long)gr1*H + c0 + j] = acc[nt][j];
                O[(long)gr2*H + c0 + j] = acc[nt][2+j];
            }
        }
    }
}

// ---------------- K3: TGL via mma.sync (256 thr, 8 warps, k-outer, gg folded) ----------------
#define TRP 104
#define TOFF_QHI 0
#define TOFF_QLO (TOFF_QHI + 128*TRP*2)
#define TOFF_KHI (TOFF_QLO + 128*TRP*2)
#define TOFF_KLO (TOFF_KHI + 128*TRP*2)
#define TOFF_CS  (TOFF_KLO + 128*TRP*2)      // [8][128] f32 colsum per band
#define TOFF_WV  (TOFF_CS + 8*128*4)         // [128] f32
#define TOFF_CTX (TOFF_WV + 128*4)           // [96] f32
#define SM_TGL   (TOFF_CTX + 96*4 + 16)      // ~111.5 KB

__global__ __launch_bounds__(256,2) void tgl_mma(
    const float* __restrict__ lng, const float* __restrict__ lnb,
    float* __restrict__ out)
{
    extern __shared__ char smem[];
    uint32_t sb = smem_u32(smem);
    int tid = threadIdx.x;
    int wid = tid >> 5, lane = tid & 31;
    int b = blockIdx.y, c = blockIdx.x;

    {
        const uint4* Qh = (const uint4*)(g_Qhi + (long)b*QLEN*H);
        const uint4* Ql = (const uint4*)(g_Qlo + (long)b*QLEN*H);
        const uint4* Kh = (const uint4*)(g_Khi + (long)c*QLEN*H);
        const uint4* Kl = (const uint4*)(g_Klo + (long)c*QLEN*H);
        uint4* dQh = (uint4*)(smem + TOFF_QHI);
        uint4* dQl = (uint4*)(smem + TOFF_QLO);
        uint4* dKh = (uint4*)(smem + TOFF_KHI);
        uint4* dKl = (uint4*)(smem + TOFF_KLO);
        for (int idx=tid; idx<128*12; idx+=256) {
            int r = idx/12, q = idx%12;
            dQh[r*13+q] = Qh[idx];
            dQl[r*13+q] = Ql[idx];
            dKh[r*13+q] = Kh[idx];
            dKl[r*13+q] = Kl[idx];
        }
    }
    __syncthreads();

    int m0 = wid*16;
    float acc[16][4];
#pragma unroll
    for (int nt=0;nt<16;nt++)
#pragma unroll
        for (int i=0;i<4;i++) acc[nt][i]=0.f;

    int rrow = m0 + (lane & 7) + ((lane >> 3) & 1) * 8;
    int rchk = ((lane >> 4) & 1) * 16;
    int brow = lane & 7;
    int bqd  = ((lane >> 3) & 3) * 16;

#pragma unroll
    for (int kc=0; kc<3; kc++) {
        uint32_t qh0[4], qh1[4], ql0[4], ql1[4];
        uint32_t abase = rrow*(TRP*2) + kc*64 + rchk;
        ldsm_x4(qh0, sb + TOFF_QHI + abase);
        ldsm_x4(qh1, sb + TOFF_QHI + abase + 32);
        ldsm_x4(ql0, sb + TOFF_QLO + abase);
        ldsm_x4(ql1, sb + TOFF_QLO + abase + 32);
#pragma unroll
        for (int nt=0; nt<16; nt++) {
            uint32_t kh[4], kl[4];
            uint32_t bbase = (nt*8+brow)*(TRP*2) + bqd + kc*64;
            ldsm_x4(kh, sb + TOFF_KHI + bbase);
            ldsm_x4(kl, sb + TOFF_KLO + bbase);
            mma16816(acc[nt], qh0, kh);
            mma16816(acc[nt], ql0, kh);
            mma16816(acc[nt], qh0, kl);
            mma16816(acc[nt], qh1, kh+2);
            mma16816(acc[nt], ql1, kh+2);
            mma16816(acc[nt], qh1, kl+2);
        }
    }

    const float SC = 0.1020620726159658f;   // 1/sqrt(96)
    float m1 = -1e30f, m2 = -1e30f;
#pragma unroll
    for (int nt=0; nt<16; nt++) {
        m1 = fmaxf(m1, fmaxf(acc[nt][0], acc[nt][1]));
        m2 = fmaxf(m2, fmaxf(acc[nt][2], acc[nt][3]));
    }
    m1 = fmaxf(m1, __shfl_xor_sync(0xffffffffu, m1, 1));
    m1 = fmaxf(m1, __shfl_xor_sync(0xffffffffu, m1, 2));
    m2 = fmaxf(m2, __shfl_xor_sync(0xffffffffu, m2, 1));
    m2 = fmaxf(m2, __shfl_xor_sync(0xffffffffu, m2, 2));

    float s1 = 0.f, s2 = 0.f;
#pragma unroll
    for (int nt=0; nt<16; nt++) {
        float e0 = __expf((acc[nt][0]-m1)*SC);
        float e1 = __expf((acc[nt][1]-m1)*SC);
        float e2 = __expf((acc[nt][2]-m2)*SC);
        float e3 = __expf((acc[nt][3]-m2)*SC);
        acc[nt][0]=e0; acc[nt][1]=e1; acc[nt][2]=e2; acc[nt][3]=e3;
        s1 += e0+e1; s2 += e2+e3;
    }
    s1 += __shfl_xor_sync(0xffffffffu, s1, 1);
    s1 += __shfl_xor_sync(0xffffffffu, s1, 2);
    s2 += __shfl_xor_sync(0xffffffffu, s2, 1);
    s2 += __shfl_xor_sync(0xffffffffu, s2, 2);
    float inv1 = 1.f/s1, inv2 = 1.f/s2;

    float* colsum = (float*)(smem + TOFF_CS);
#pragma unroll
    for (int nt=0; nt<16; nt++) {
        float v0 = acc[nt][0]*inv1 + acc[nt][2]*inv2;
        float v1 = acc[nt][1]*inv1 + acc[nt][3]*inv2;
#pragma unroll
        for (int o=4; o<32; o<<=1) {
            v0 += __shfl_xor_sync(0xffffffffu, v0, o);
            v1 += __shfl_xor_sync(0xffffffffu, v1, o);
        }
        if (lane < 4) {
            colsum[wid*128 + nt*8 + lane*2]     = v0;
            colsum[wid*128 + nt*8 + lane*2 + 1] = v1;
        }
    }
    __syncthreads();

    float* wv = (float*)(smem + TOFF_WV);
    if (tid < 128) {
        float s = 0.f;
#pragma unroll
        for (int w=0; w<8; w++) s += colsum[w*128 + tid];
        wv[tid] = s * (1.f/128.f);
    }
    __syncthreads();

    float* ctxs = (float*)(smem + TOFF_CTX);
    if (tid < 96) {
        const float* Vr = g_Vt + (long)c*H*QLEN + tid*QLEN;
        float s = 0.f;
#pragma unroll
        for (int k4=0;k4<QLEN/4;k4++) {
            float4 v = ((const float4*)Vr)[k4];
            s += wv[k4*4]*v.x + wv[k4*4+1]*v.y + wv[k4*4+2]*v.z + wv[k4*4+3]*v.w;
        }
        ctxs[tid] = s;
    }
    __syncthreads();

    if (tid < 32) {
        float x0=ctxs[tid], x1=ctxs[tid+32], x2=ctxs[tid+64];
        float mu = x0+x1+x2;
#pragma unroll
        for (int o=16;o;o>>=1) mu += __shfl_xor_sync(0xffffffffu,mu,o);
        mu *= (1.f/96.f);
        float d0=x0-mu, d1=x1-mu, d2=x2-mu;
        float var = d0*d0 + d1*d1 + d2*d2;
#pragma unroll
        for (int o=16;o;o>>=1) var += __shfl_xor_sync(0xffffffffu,var,o);
        var *= (1.f/96.f);
        float rstd = rsqrtf(var + 1e-5f);
        float n0v = d0*rstd*lng[tid]    + lnb[tid];
        float n1v = d1*rstd*lng[tid+32] + lnb[tid+32];
        float n2v = d2*rstd*lng[tid+64] + lnb[tid+64];
        float ss = n0v*n0v + n1v*n1v + n2v*n2v;
#pragma unroll
        for (int o=16;o;o>>=1) ss += __shfl_xor_sync(0xffffffffu,ss,o);
        float sc = 1.f / fmaxf(sqrtf(ss), 1e-6f);
        const float* db = g_d + b*H;
        const float* tb = g_t + b*H;
        const float* dc = g_d + c*H;
        const float* vc = g_v + c*H;
        float part = (db[tid]*n0v + db[tid+32]*n1v + db[tid+64]*n2v)*sc
                   + tb[tid]   *(dc[tid]   +vc[tid])
                   + tb[tid+32]*(dc[tid+32]+vc[tid+32])
                   + tb[tid+64]*(dc[tid+64]+vc[tid+64]);
#pragma unroll
        for (int o=16;o;o>>=1) part += __shfl_xor_sync(0xffffffffu,part,o);
        if (tid==0) out[b*64+c] = 0.5f * part;
    }
}

// ---------------- K4: CLL via mma.sync (256 thr, 8 warps, chunked B) ----------------
#define RPAD 104
#define COFF_AHI 0
#define COFF_ALO (COFF_AHI + 128*RPAD*2)
#define COFF_BHI (COFF_ALO + 128*RPAD*2)       // chunk buffer: 104 rows
#define COFF_BLO (COFF_BHI + 104*RPAD*2)
#define COFF_RED (COFF_BLO + 104*RPAD*2)
#define SM_CLL  (COFF_RED + 64)                // ~96.6 KB

__global__ __launch_bounds__(256,2) void cll_mma(float* __restrict__ out)
{
    extern __shared__ char smem[];
    uint32_t sb = smem_u32(smem);
    int tid = threadIdx.x;
    int wid = tid >> 5, lane = tid & 31;
    int b = blockIdx.y, c = blockIdx.x;

    const uint4* Bh = (const uint4*)(g_Bhi + (long)c*PLEN*H);
    const uint4* Bl = (const uint4*)(g_Blo + (long)c*PLEN*H);
    uint4* dBh = (uint4*)(smem + COFF_BHI);
    uint4* dBl = (uint4*)(smem + COFF_BLO);

    {
        const uint4* Ah = (const uint4*)(g_Ahi + (long)b*QLEN*H);
        const uint4* Al = (const uint4*)(g_Alo + (long)b*QLEN*H);
        uint4* dAh = (uint4*)(smem + COFF_AHI);
        uint4* dAl = (uint4*)(smem + COFF_ALO);
        for (int idx=tid; idx<128*12; idx+=256) {
            int r = idx/12, q = idx%12;
            dAh[r*13+q] = Ah[idx];
            dAl[r*13+q] = Al[idx];
        }
        for (int idx=tid; idx<104*12; idx+=256) {
            int r = idx/12, q = idx%12;
            dBh[r*13+q] = Bh[idx];
            dBl[r*13+q] = Bl[idx];
        }
    }
    __syncthreads();

    int m0 = wid*16;
    uint32_t ahi[6][4], alo[6][4];
    {
        int rrow = m0 + (lane & 7) + ((lane >> 3) & 1) * 8;
        int rchk = ((lane >> 4) & 1) * 16;
#pragma unroll
        for (int ks=0; ks<6; ks++) {
            ldsm_x4(ahi[ks], sb + COFF_AHI + rrow*(RPAD*2) + ks*32 + rchk);
            ldsm_x4(alo[ks], sb + COFF_ALO + rrow*(RPAD*2) + ks*32 + rchk);
        }
    }

    float mbest = -1e30f;
    int brow = lane & 7;
    int bqd  = ((lane >> 3) & 3) * 16;

    for (int nt=0; nt<13; nt++) {
        float a0[4]={0.f,0.f,0.f,0.f}, a1[4]={0.f,0.f,0.f,0.f};
        uint32_t baddr_h = sb + COFF_BHI + (nt*8+brow)*(RPAD*2) + bqd;
        uint32_t baddr_l = sb + COFF_BLO + (nt*8+brow)*(RPAD*2) + bqd;
#pragma unroll
        for (int ks2=0; ks2<3; ks2++) {
            uint32_t bh[4], bl[4];
            ldsm_x4(bh, baddr_h + ks2*64);
            ldsm_x4(bl, baddr_l + ks2*64);
            mma16816(a0, ahi[2*ks2],   bh);
            mma16816(a1, alo[2*ks2],   bh);
            mma16816(a0, ahi[2*ks2],   bl);
            mma16816(a1, ahi[2*ks2+1], bh+2);
            mma16816(a0, alo[2*ks2+1], bh+2);
            mma16816(a1, ahi[2*ks2+1], bl+2);
        }
        mbest = fmaxf(mbest, fmaxf(fmaxf(a0[0]+a1[0], a0[1]+a1[1]),
                                   fmaxf(a0[2]+a1[2], a0[3]+a1[3])));
    }

    __syncthreads();

    for (int idx=tid; idx<92*12; idx+=256) {
        int r = idx/12, q = idx%12;
        dBh[r*13+q] = Bh[(104+r)*12+q];
        dBl[r*13+q] = Bl[(104+r)*12+q];
    }
    {
        uint4 z = make_uint4(0,0,0,0);
        for (int idx=tid; idx<4*13; idx+=256) {
            int r = 92 + idx/13, q = idx%13;
            dBh[r*13+q] = z;
            dBl[r*13+q] = z;
        }
    }
    __syncthreads();

    for (int nt=13; nt<25; nt++) {
        float a0[4]={0.f,0.f,0.f,0.f}, a1[4]={0.f,0.f,0.f,0.f};
        int ln0 = nt*8 - 104;
        uint32_t baddr_h = sb + COFF_BHI + (ln0+brow)*(RPAD*2) + bqd;
        uint32_t baddr_l = sb + COFF_BLO + (ln0+brow)*(RPAD*2) + bqd;
#pragma unroll
        for (int ks2=0; ks2<3; ks2++) {
            uint32_t bh[4], bl[4];
            ldsm_x4(bh, baddr_h + ks2*64);
            ldsm_x4(bl, baddr_l + ks2*64);
            mma16816(a0, ahi[2*ks2],   bh);
            mma16816(a1, alo[2*ks2],   bh);
            mma16816(a0, ahi[2*ks2],   bl);
            mma16816(a1, ahi[2*ks2+1], bh+2);
            mma16816(a0, alo[2*ks2+1], bh+2);
            mma16816(a1, ahi[2*ks2+1], bl+2);
        }
        int col0 = nt*8 + (lane & 3)*2;
        if (col0 < PLEN)   mbest = fmaxf(mbest, fmaxf(a0[0]+a1[0], a0[2]+a1[2]));
        if (col0+1 < PLEN) mbest = fmaxf(mbest, fmaxf(a0[1]+a1[1], a0[3]+a1[3]));
    }

#pragma unroll
    for (int o=16;o;o>>=1) mbest = fmaxf(mbest, __shfl_xor_sync(0xffffffffu,mbest,o));
    float* red = (float*)(smem + COFF_RED);
    if (lane == 0) red[wid] = mbest;
    __syncthreads();
    if (tid == 0) {
        float m = red[0];
#pragma unroll
        for (int w=1;w<8;w++) m = fmaxf(m, red[w]);
        out[b*64+c] += 0.5f*m;
    }
}

// ---------------- host ----------------
extern "C" void kernel_launch(void* const* d_in, const int* in_sizes, int n_in,
                              void* d_out, int out_size)
{
    const float* z_d_cls = (const float*)d_in[0];
    const float* Z_d_tok = (const float*)d_in[1];
    const float* z_t_cls = (const float*)d_in[2];
    const float* Z_t_tok = (const float*)d_in[3];
    const float* z_v_cls = (const float*)d_in[4];
    const float* Z_v_pat = (const float*)d_in[5];
    const float *W_t_cls=(const float*)d_in[6],  *b_t_cls=(const float*)d_in[7];
    const float *W_d_cls=(const float*)d_in[8],  *b_d_cls=(const float*)d_in[9];
    const float *W_v_cls=(const float*)d_in[10], *b_v_cls=(const float*)d_in[11];
    const float *W_t_tok=(const float*)d_in[12], *b_t_tok=(const float*)d_in[13];
    const float *W_v_pat=(const float*)d_in[14], *b_v_pat=(const float*)d_in[15];
    const float *W_q=(const float*)d_in[16], *b_q=(const float*)d_in[17];
    const float *W_k=(const float*)d_in[18], *b_k=(const float*)d_in[19];
    const float *W_v=(const float*)d_in[20], *b_v=(const float*)d_in[21];
    const float *ln_g=(const float*)d_in[22], *ln_b=(const float*)d_in[23];
    float* out = (float*)d_out;

    float *Vp,*tp,*dp,*vp;
    void *qhi,*qlo,*khi,*klo,*ahi,*alo,*bhi,*blo;
    cudaGetSymbolAddress((void**)&Vp,  g_Vt);
    cudaGetSymbolAddress((void**)&tp,  g_t);
    cudaGetSymbolAddress((void**)&dp,  g_d);
    cudaGetSymbolAddress((void**)&vp,  g_v);
    cudaGetSymbolAddress(&qhi, g_Qhi);
    cudaGetSymbolAddress(&qlo, g_Qlo);
    cudaGetSymbolAddress(&khi, g_Khi);
    cudaGetSymbolAddress(&klo, g_Klo);
    cudaGetSymbolAddress(&ahi, g_Ahi);
    cudaGetSymbolAddress(&alo, g_Alo);
    cudaGetSymbolAddress(&bhi, g_Bhi);
    cudaGetSymbolAddress(&blo, g_Blo);

    cudaFuncSetAttribute(proj_mma, cudaFuncAttributeMaxDynamicSharedMemorySize, SM_PROJ);
    cudaFuncSetAttribute(tgl_mma,  cudaFuncAttributeMaxDynamicSharedMemorySize, SM_TGL);
    cudaFuncSetAttribute(cll_mma,  cudaFuncAttributeMaxDynamicSharedMemorySize, SM_CLL);

    ProjArgs pa;
    for (int i=0;i<8;i++) { pa.Out2[i]=nullptr; pa.mode[i]=0; pa.L[i]=0; pa.l2n[i]=0; }
    pa.X[0]=Z_d_tok; pa.W[0]=W_q;     pa.Bv[0]=b_q;     pa.Out[0]=(float*)qhi; pa.Out2[0]=qlo; pa.mode[0]=1;
    pa.X[1]=Z_t_tok; pa.W[1]=W_k;     pa.Bv[1]=b_k;     pa.Out[1]=(float*)khi; pa.Out2[1]=klo; pa.mode[1]=1;
    pa.X[2]=Z_t_tok; pa.W[2]=W_v;     pa.Bv[2]=b_v;     pa.Out[2]=Vp;  pa.L[2]=QLEN;
    pa.X[3]=Z_t_tok; pa.W[3]=W_t_tok; pa.Bv[3]=b_t_tok; pa.Out[3]=(float*)ahi; pa.Out2[3]=alo; pa.l2n[3]=1; pa.mode[3]=1;
    pa.X[4]=Z_v_pat; pa.W[4]=W_v_pat; pa.Bv[4]=b_v_pat; pa.Out[4]=(float*)bhi; pa.Out2[4]=blo; pa.l2n[4]=1; pa.mode[4]=2;
    pa.X[5]=z_t_cls; pa.W[5]=W_t_cls; pa.Bv[5]=b_t_cls; pa.Out[5]=tp;  pa.l2n[5]=1;
    pa.X[6]=z_d_cls; pa.W[6]=W_d_cls; pa.Bv[6]=b_d_cls; pa.Out[6]=dp;  pa.l2n[6]=1;
    pa.X[7]=z_v_cls; pa.W[7]=W_v_cls; pa.Bv[7]=b_v_cls; pa.Out[7]=vp;  pa.l2n[7]=1;
    int nt[8] = {128,128,128,128,196,1,1,1};
    pa.tile_start[0]=0;
    for (int i=0;i<8;i++) pa.tile_start[i+1]=pa.tile_start[i]+nt[i];

    proj_mma<<<pa.tile_start[8],256,SM_PROJ>>>(pa);

    // out = 0.5*(S_TGG + S_CGG + S_TGL)   (gg folded, "=" write)
    tgl_mma<<<dim3(64,64),256,SM_TGL>>>(ln_g, ln_b, out);
    // out += 0.5*S_CLL
    cll_mma<<<dim3(64,64),256,SM_CLL>>>(out);
}

// round 12
// speedup vs baseline: 1.6524x; 1.0267x over previous
#include <cuda_runtime.h>
#include <cuda_bf16.h>
#include <cstdint>

#define EIN 512
#define H   96
#define BSZ 64
#define QLEN 128
#define PLEN 196

// ---------------- scratch (device globals; zero-initialized) ----------------
__device__ float g_Vt [BSZ*H*QLEN];   // [c][h][q] h-major fp32
__device__ float g_t [BSZ*H];
__device__ float g_d [BSZ*H];
__device__ float g_v [BSZ*H];

// bf16 hi/lo split operands (plain row-major [b][row][h])
__device__ __nv_bfloat16 g_Qhi[BSZ*QLEN*H];
__device__ __nv_bfloat16 g_Qlo[BSZ*QLEN*H];
__device__ __nv_bfloat16 g_Khi[BSZ*QLEN*H];
__device__ __nv_bfloat16 g_Klo[BSZ*QLEN*H];
__device__ __nv_bfloat16 g_Ahi[BSZ*QLEN*H];   // t_tok
__device__ __nv_bfloat16 g_Alo[BSZ*QLEN*H];
__device__ __nv_bfloat16 g_Bhi[BSZ*PLEN*H];   // v_patch
__device__ __nv_bfloat16 g_Blo[BSZ*PLEN*H];

// ---------------- PTX helpers ----------------
__device__ __forceinline__ uint32_t smem_u32(const void* p) {
    uint32_t a;
    asm("{ .reg .u64 t; cvta.to.shared.u64 t, %1; cvt.u32.u64 %0, t; }"
        : "=r"(a) : "l"(p));
    return a;
}
__device__ __forceinline__ void ldsm_x4(uint32_t* r, uint32_t addr) {
    asm volatile("ldmatrix.sync.aligned.m8n8.x4.shared.b16 {%0,%1,%2,%3}, [%4];"
        : "=r"(r[0]),"=r"(r[1]),"=r"(r[2]),"=r"(r[3]) : "r"(addr));
}
__device__ __forceinline__ void mma16816(float* d, const uint32_t* a, const uint32_t* b) {
    asm volatile("mma.sync.aligned.m16n8k16.row.col.f32.bf16.bf16.f32 "
        "{%0,%1,%2,%3}, {%4,%5,%6,%7}, {%8,%9}, {%0,%1,%2,%3};"
        : "+f"(d[0]),"+f"(d[1]),"+f"(d[2]),"+f"(d[3])
        : "r"(a[0]),"r"(a[1]),"r"(a[2]),"r"(a[3]), "r"(b[0]),"r"(b[1]));
}
__device__ __forceinline__ uint32_t pack_hi2(float x, float y) {
    __nv_bfloat162 h = __floats2bfloat162_rn(x, y);
    return *(uint32_t*)&h;
}
#define CP_ASYNC16(dst, src) \
    asm volatile("cp.async.cg.shared.global [%0], [%1], 16;" \
                 :: "r"(dst), "l"(src) : "memory")
#define CP_COMMIT() asm volatile("cp.async.commit_group;" ::: "memory")
#define CP_WAIT0()  asm volatile("cp.async.wait_group 0;" ::: "memory")

// ---------------- K1: batched projection via mma.sync split-bf16 ----------------
struct ProjArgs {
    const float* X[8];
    const float* W[8];
    const float* Bv[8];
    float*       Out[8];
    void*        Out2[8];
    int          tile_start[9];
    int          l2n[8];
    int          L[8];       // >0 (mode 0): fp32 transposed [row/L][96][L]
    int          mode[8];    // 0: fp32, 1: bf16 split 128 rows/b, 2: bf16 split 196 rows/c
};

#define PRP  136                                 // padded row: 136 bf16 = 272 B
#define POFF_XHI 0
#define POFF_XLO (POFF_XHI + 64*PRP*2)
#define POFF_WHI (POFF_XLO + 64*PRP*2)
#define POFF_WLO (POFF_WHI + 96*PRP*2)
#define POFF_RED (POFF_WLO + 96*PRP*2)           // [64][2] f32 partial ss
#define SM_PROJ  (POFF_RED + 64*2*4 + 16)        // ~87.6 KB

__global__ __launch_bounds__(256,2) void proj_mma(ProjArgs pa)
{
    extern __shared__ char smem[];
    uint32_t sb = smem_u32(smem);
    int tid = threadIdx.x;
    int wid = tid >> 5, lane = tid & 31;
    int band = wid & 3, nhalf = wid >> 2;

    int bid = blockIdx.x;
    int mi = 0;
#pragma unroll
    for (int i=1;i<8;i++) if (bid >= pa.tile_start[i]) mi = i;
    int tile = bid - pa.tile_start[mi];

    const float* Xb = pa.X[mi] + (long)tile*64*EIN;
    const float* W  = pa.W[mi];

    float acc[6][4];
#pragma unroll
    for (int nt=0;nt<6;nt++)
#pragma unroll
        for (int i=0;i<4;i++) acc[nt][i]=0.f;

    int rrow = band*16 + (lane & 7) + ((lane >> 3) & 1) * 8;
    int rchk = ((lane >> 4) & 1) * 16;
    int brow = lane & 7;
    int bqd  = ((lane >> 3) & 3) * 16;

    for (int kc=0; kc<4; kc++) {
        __syncthreads();
        for (int idx=tid; idx<64*32; idx+=256) {
            int r = idx>>5, k4 = idx&31;
            float4 x = *(const float4*)(Xb + r*EIN + kc*128 + k4*4);
            __nv_bfloat16 h0=__float2bfloat16(x.x), h1=__float2bfloat16(x.y),
                          h2=__float2bfloat16(x.z), h3=__float2bfloat16(x.w);
            uint2 hw, lw;
            hw.x = pack_hi2(x.x, x.y); hw.y = pack_hi2(x.z, x.w);
            lw.x = pack_hi2(x.x-__bfloat162float(h0), x.y-__bfloat162float(h1));
            lw.y = pack_hi2(x.z-__bfloat162float(h2), x.w-__bfloat162float(h3));
            *(uint2*)(smem + POFF_XHI + r*(PRP*2) + k4*8) = hw;
            *(uint2*)(smem + POFF_XLO + r*(PRP*2) + k4*8) = lw;
        }
        for (int idx=tid; idx<96*32; idx+=256) {
            int r = idx>>5, k4 = idx&31;
            float4 x = *(const float4*)(W + r*EIN + kc*128 + k4*4);
            __nv_bfloat16 h0=__float2bfloat16(x.x), h1=__float2bfloat16(x.y),
                          h2=__float2bfloat16(x.z), h3=__float2bfloat16(x.w);
            uint2 hw, lw;
            hw.x = pack_hi2(x.x, x.y); hw.y = pack_hi2(x.z, x.w);
            lw.x = pack_hi2(x.x-__bfloat162float(h0), x.y-__bfloat162float(h1));
            lw.y = pack_hi2(x.z-__bfloat162float(h2), x.w-__bfloat162float(h3));
            *(uint2*)(smem + POFF_WHI + r*(PRP*2) + k4*8) = hw;
            *(uint2*)(smem + POFF_WLO + r*(PRP*2) + k4*8) = lw;
        }
        __syncthreads();

#pragma unroll
        for (int ks2=0; ks2<4; ks2++) {
            uint32_t xh0[4], xh1[4], xl0[4], xl1[4];
            uint32_t abase = rrow*(PRP*2) + ks2*64 + rchk;
            ldsm_x4(xh0, sb + POFF_XHI + abase);
            ldsm_x4(xh1, sb + POFF_XHI + abase + 32);
            ldsm_x4(xl0, sb + POFF_XLO + abase);
            ldsm_x4(xl1, sb + POFF_XLO + abase + 32);
#pragma unroll
            for (int nt=0; nt<6; nt++) {
                uint32_t wh[4], wl[4];
                uint32_t bbase = (nhalf*48+nt*8+brow)*(PRP*2) + bqd + ks2*64;
                ldsm_x4(wh, sb + POFF_WHI + bbase);
                ldsm_x4(wl, sb + POFF_WLO + bbase);
                mma16816(acc[nt], xh0, wh);
                mma16816(acc[nt], xl0, wh);
                mma16816(acc[nt], xh0, wl);
                mma16816(acc[nt], xh1, wh+2);
                mma16816(acc[nt], xl1, wh+2);
                mma16816(acc[nt], xh1, wl+2);
            }
        }
    }

    int r1 = band*16 + (lane >> 2), r2 = r1 + 8;
    const float* bias = pa.Bv[mi];
#pragma unroll
    for (int nt=0; nt<6; nt++) {
        int c0 = nhalf*48 + nt*8 + (lane & 3)*2;
        float b0 = bias[c0], b1 = bias[c0+1];
        acc[nt][0] += b0; acc[nt][1] += b1;
        acc[nt][2] += b0; acc[nt][3] += b1;
    }

    if (pa.l2n[mi]) {
        float ss1 = 0.f, ss2 = 0.f;
#pragma unroll
        for (int nt=0; nt<6; nt++) {
            ss1 += acc[nt][0]*acc[nt][0] + acc[nt][1]*acc[nt][1];
            ss2 += acc[nt][2]*acc[nt][2] + acc[nt][3]*acc[nt][3];
        }
        ss1 += __shfl_xor_sync(0xffffffffu, ss1, 1);
        ss1 += __shfl_xor_sync(0xffffffffu, ss1, 2);
        ss2 += __shfl_xor_sync(0xffffffffu, ss2, 1);
        ss2 += __shfl_xor_sync(0xffffffffu, ss2, 2);
        float* red = (float*)(smem + POFF_RED);
        __syncthreads();
        if ((lane & 3) == 0) {
            red[r1*2 + nhalf] = ss1;
            red[r2*2 + nhalf] = ss2;
        }
        __syncthreads();
        float sc1 = 1.f / fmaxf(sqrtf(red[r1*2] + red[r1*2+1]), 1e-6f);
        float sc2 = 1.f / fmaxf(sqrtf(red[r2*2] + red[r2*2+1]), 1e-6f);
#pragma unroll
        for (int nt=0; nt<6; nt++) {
            acc[nt][0] *= sc1; acc[nt][1] *= sc1;
            acc[nt][2] *= sc2; acc[nt][3] *= sc2;
        }
    }

    int mode = pa.mode[mi];
    int gr1 = tile*64 + r1, gr2 = tile*64 + r2;
    if (mode) {
        int perlen = (mode==1) ? 128 : 196;
        __nv_bfloat16* hiB = (__nv_bfloat16*)pa.Out[mi];
        __nv_bfloat16* loB = (__nv_bfloat16*)pa.Out2[mi];
        int bb1 = gr1/perlen, rr1 = gr1 - bb1*perlen;
        int bb2 = gr2/perlen, rr2 = gr2 - bb2*perlen;
        long base1 = ((long)bb1*perlen + rr1)*H;
        long base2 = ((long)bb2*perlen + rr2)*H;
#pragma unroll
        for (int nt=0; nt<6; nt++) {
            int c0 = nhalf*48 + nt*8 + (lane & 3)*2;
#pragma unroll
            for (int j=0;j<2;j++) {
                float v1 = acc[nt][j], v2 = acc[nt][2+j];
                __nv_bfloat16 h1v = __float2bfloat16(v1);
                __nv_bfloat16 h2v = __float2bfloat16(v2);
                hiB[base1 + c0 + j] = h1v;
                loB[base1 + c0 + j] = __float2bfloat16(v1 - __bfloat162float(h1v));
                hiB[base2 + c0 + j] = h2v;
                loB[base2 + c0 + j] = __float2bfloat16(v2 - __bfloat162float(h2v));
            }
        }
    } else if (pa.L[mi] > 0) {
        int L = pa.L[mi];
        float* O = pa.Out[mi];
        int bb1 = gr1/L, pp1 = gr1 - bb1*L;
        int bb2 = gr2/L, pp2 = gr2 - bb2*L;
#pragma unroll
        for (int nt=0; nt<6; nt++) {
            int c0 = nhalf*48 + nt*8 + (lane & 3)*2;
#pragma unroll
            for (int j=0;j<2;j++) {
                O[((long)bb1*H + c0 + j)*L + pp1] = acc[nt][j];
                O[((long)bb2*H + c0 + j)*L + pp2] = acc[nt][2+j];
            }
        }
    } else {
        float* O = pa.Out[mi];
#pragma unroll
        for (int nt=0; nt<6; nt++) {
            int c0 = nhalf*48 + nt*8 + (lane & 3)*2;
#pragma unroll
            for (int j=0;j<2;j++) {
                O[(long)gr1*H + c0 + j] = acc[nt][j];
                O[(long)gr2*H + c0 + j] = acc[nt][2+j];
            }
        }
    }
}

// ---------------- K3: TGL via mma.sync (256 thr, 8 warps, prefetched B frags) ----------------
#define TRP 104
#define TOFF_QHI 0
#define TOFF_QLO (TOFF_QHI + 128*TRP*2)
#define TOFF_KHI (TOFF_QLO + 128*TRP*2)
#define TOFF_KLO (TOFF_KHI + 128*TRP*2)
#define TOFF_CS  (TOFF_KLO + 128*TRP*2)      // [8][128] f32 colsum per band
#define TOFF_WV  (TOFF_CS + 8*128*4)         // [128] f32
#define TOFF_CTX (TOFF_WV + 128*4)           // [96] f32
#define SM_TGL   (TOFF_CTX + 96*4 + 16)      // ~111.5 KB

__global__ __launch_bounds__(256,2) void tgl_mma(
    const float* __restrict__ lng, const float* __restrict__ lnb,
    float* __restrict__ out)
{
    extern __shared__ char smem[];
    uint32_t sb = smem_u32(smem);
    int tid = threadIdx.x;
    int wid = tid >> 5, lane = tid & 31;
    int b = blockIdx.y, c = blockIdx.x;

    {
        const uint4* Qh = (const uint4*)(g_Qhi + (long)b*QLEN*H);
        const uint4* Ql = (const uint4*)(g_Qlo + (long)b*QLEN*H);
        const uint4* Kh = (const uint4*)(g_Khi + (long)c*QLEN*H);
        const uint4* Kl = (const uint4*)(g_Klo + (long)c*QLEN*H);
        uint4* dQh = (uint4*)(smem + TOFF_QHI);
        uint4* dQl = (uint4*)(smem + TOFF_QLO);
        uint4* dKh = (uint4*)(smem + TOFF_KHI);
        uint4* dKl = (uint4*)(smem + TOFF_KLO);
        for (int idx=tid; idx<128*12; idx+=256) {
            int r = idx/12, q = idx%12;
            dQh[r*13+q] = Qh[idx];
            dQl[r*13+q] = Ql[idx];
            dKh[r*13+q] = Kh[idx];
            dKl[r*13+q] = Kl[idx];
        }
    }
    __syncthreads();

    int m0 = wid*16;
    float acc[16][4];
#pragma unroll
    for (int nt=0;nt<16;nt++)
#pragma unroll
        for (int i=0;i<4;i++) acc[nt][i]=0.f;

    int rrow = m0 + (lane & 7) + ((lane >> 3) & 1) * 8;
    int rchk = ((lane >> 4) & 1) * 16;
    int brow = lane & 7;
    int bqd  = ((lane >> 3) & 3) * 16;

#pragma unroll
    for (int kc=0; kc<3; kc++) {
        uint32_t qh0[4], qh1[4], ql0[4], ql1[4];
        uint32_t abase = rrow*(TRP*2) + kc*64 + rchk;
        ldsm_x4(qh0, sb + TOFF_QHI + abase);
        ldsm_x4(qh1, sb + TOFF_QHI + abase + 32);
        ldsm_x4(ql0, sb + TOFF_QLO + abase);
        ldsm_x4(ql1, sb + TOFF_QLO + abase + 32);

        uint32_t kh[2][4], kl[2][4];
        {
            uint32_t bb0 = brow*(TRP*2) + bqd + kc*64;
            ldsm_x4(kh[0], sb + TOFF_KHI + bb0);
            ldsm_x4(kl[0], sb + TOFF_KLO + bb0);
        }
#pragma unroll
        for (int nt=0; nt<16; nt++) {
            int cur = nt & 1;
            if (nt < 15) {
                uint32_t bb = ((nt+1)*8+brow)*(TRP*2) + bqd + kc*64;
                ldsm_x4(kh[cur^1], sb + TOFF_KHI + bb);
                ldsm_x4(kl[cur^1], sb + TOFF_KLO + bb);
            }
            mma16816(acc[nt], qh0, kh[cur]);
            mma16816(acc[nt], ql0, kh[cur]);
            mma16816(acc[nt], qh0, kl[cur]);
            mma16816(acc[nt], qh1, kh[cur]+2);
            mma16816(acc[nt], ql1, kh[cur]+2);
            mma16816(acc[nt], qh1, kl[cur]+2);
        }
    }

    const float SC = 0.1020620726159658f;   // 1/sqrt(96)
    float m1 = -1e30f, m2 = -1e30f;
#pragma unroll
    for (int nt=0; nt<16; nt++) {
        m1 = fmaxf(m1, fmaxf(acc[nt][0], acc[nt][1]));
        m2 = fmaxf(m2, fmaxf(acc[nt][2], acc[nt][3]));
    }
    m1 = fmaxf(m1, __shfl_xor_sync(0xffffffffu, m1, 1));
    m1 = fmaxf(m1, __shfl_xor_sync(0xffffffffu, m1, 2));
    m2 = fmaxf(m2, __shfl_xor_sync(0xffffffffu, m2, 1));
    m2 = fmaxf(m2, __shfl_xor_sync(0xffffffffu, m2, 2));

    float s1 = 0.f, s2 = 0.f;
#pragma unroll
    for (int nt=0; nt<16; nt++) {
        float e0 = __expf((acc[nt][0]-m1)*SC);
        float e1 = __expf((acc[nt][1]-m1)*SC);
        float e2 = __expf((acc[nt][2]-m2)*SC);
        float e3 = __expf((acc[nt][3]-m2)*SC);
        acc[nt][0]=e0; acc[nt][1]=e1; acc[nt][2]=e2; acc[nt][3]=e3;
        s1 += e0+e1; s2 += e2+e3;
    }
    s1 += __shfl_xor_sync(0xffffffffu, s1, 1);
    s1 += __shfl_xor_sync(0xffffffffu, s1, 2);
    s2 += __shfl_xor_sync(0xffffffffu, s2, 1);
    s2 += __shfl_xor_sync(0xffffffffu, s2, 2);
    float inv1 = 1.f/s1, inv2 = 1.f/s2;

    float* colsum = (float*)(smem + TOFF_CS);
#pragma unroll
    for (int nt=0; nt<16; nt++) {
        float v0 = acc[nt][0]*inv1 + acc[nt][2]*inv2;
        float v1 = acc[nt][1]*inv1 + acc[nt][3]*inv2;
#pragma unroll
        for (int o=4; o<32; o<<=1) {
            v0 += __shfl_xor_sync(0xffffffffu, v0, o);
            v1 += __shfl_xor_sync(0xffffffffu, v1, o);
        }
        if (lane < 4) {
            colsum[wid*128 + nt*8 + lane*2]     = v0;
            colsum[wid*128 + nt*8 + lane*2 + 1] = v1;
        }
    }
    __syncthreads();

    float* wv = (float*)(smem + TOFF_WV);
    if (tid < 128) {
        float s = 0.f;
#pragma unroll
        for (int w=0; w<8; w++) s += colsum[w*128 + tid];
        wv[tid] = s * (1.f/128.f);
    }
    __syncthreads();

    float* ctxs = (float*)(smem + TOFF_CTX);
    if (tid < 96) {
        const float* Vr = g_Vt + (long)c*H*QLEN + tid*QLEN;
        float s = 0.f;
#pragma unroll
        for (int k4=0;k4<QLEN/4;k4++) {
            float4 v = ((const float4*)Vr)[k4];
            s += wv[k4*4]*v.x + wv[k4*4+1]*v.y + wv[k4*4+2]*v.z + wv[k4*4+3]*v.w;
        }
        ctxs[tid] = s;
    }
    __syncthreads();

    if (tid < 32) {
        float x0=ctxs[tid], x1=ctxs[tid+32], x2=ctxs[tid+64];
        float mu = x0+x1+x2;
#pragma unroll
        for (int o=16;o;o>>=1) mu += __shfl_xor_sync(0xffffffffu,mu,o);
        mu *= (1.f/96.f);
        float d0=x0-mu, d1=x1-mu, d2=x2-mu;
        float var = d0*d0 + d1*d1 + d2*d2;
#pragma unroll
        for (int o=16;o;o>>=1) var += __shfl_xor_sync(0xffffffffu,var,o);
        var *= (1.f/96.f);
        float rstd = rsqrtf(var + 1e-5f);
        float n0v = d0*rstd*lng[tid]    + lnb[tid];
        float n1v = d1*rstd*lng[tid+32] + lnb[tid+32];
        float n2v = d2*rstd*lng[tid+64] + lnb[tid+64];
        float ss = n0v*n0v + n1v*n1v + n2v*n2v;
#pragma unroll
        for (int o=16;o;o>>=1) ss += __shfl_xor_sync(0xffffffffu,ss,o);
        float sc = 1.f / fmaxf(sqrtf(ss), 1e-6f);
        const float* db = g_d + b*H;
        const float* tb = g_t + b*H;
        const float* dc = g_d + c*H;
        const float* vc = g_v + c*H;
        float part = (db[tid]*n0v + db[tid+32]*n1v + db[tid+64]*n2v)*sc
                   + tb[tid]   *(dc[tid]   +vc[tid])
                   + tb[tid+32]*(dc[tid+32]+vc[tid+32])
                   + tb[tid+64]*(dc[tid+64]+vc[tid+64]);
#pragma unroll
        for (int o=16;o;o>>=1) part += __shfl_xor_sync(0xffffffffu,part,o);
        if (tid==0) out[b*64+c] = 0.5f * part;
    }
}

// ---------------- K4: CLL via mma.sync (256 thr, chunked B + cp.async overlap) ----------------
#define RPAD 104
#define COFF_AHI 0
#define COFF_ALO (COFF_AHI + 128*RPAD*2)
#define COFF_BHI (COFF_ALO + 128*RPAD*2)       // chunk0 buffer: 104 rows
#define COFF_BLO (COFF_BHI + 104*RPAD*2)
#define COFF_RED (COFF_BLO + 104*RPAD*2)
#define SM_CLL  (COFF_RED + 64)                // ~96.6 KB

__global__ __launch_bounds__(256,2) void cll_mma(float* __restrict__ out)
{
    extern __shared__ char smem[];
    uint32_t sb = smem_u32(smem);
    int tid = threadIdx.x;
    int wid = tid >> 5, lane = tid & 31;
    int b = blockIdx.y, c = blockIdx.x;

    const uint4* Bh = (const uint4*)(g_Bhi + (long)c*PLEN*H);
    const uint4* Bl = (const uint4*)(g_Blo + (long)c*PLEN*H);
    uint4* dBh = (uint4*)(smem + COFF_BHI);
    uint4* dBl = (uint4*)(smem + COFF_BLO);

    // load A full + B chunk0 (rows 0..103)
    {
        const uint4* Ah = (const uint4*)(g_Ahi + (long)b*QLEN*H);
        const uint4* Al = (const uint4*)(g_Alo + (long)b*QLEN*H);
        uint4* dAh = (uint4*)(smem + COFF_AHI);
        uint4* dAl = (uint4*)(smem + COFF_ALO);
        for (int idx=tid; idx<128*12; idx+=256) {
            int r = idx/12, q = idx%12;
            dAh[r*13+q] = Ah[idx];
            dAl[r*13+q] = Al[idx];
        }
        for (int idx=tid; idx<104*12; idx+=256) {
            int r = idx/12, q = idx%12;
            dBh[r*13+q] = Bh[idx];
            dBl[r*13+q] = Bl[idx];
        }
    }
    __syncthreads();

    // A fragments (registers; A smem becomes dead after this)
    int m0 = wid*16;
    uint32_t ahi[6][4], alo[6][4];
    {
        int rrow = m0 + (lane & 7) + ((lane >> 3) & 1) * 8;
        int rchk = ((lane >> 4) & 1) * 16;
#pragma unroll
        for (int ks=0; ks<6; ks++) {
            ldsm_x4(ahi[ks], sb + COFF_AHI + rrow*(RPAD*2) + ks*32 + rchk);
            ldsm_x4(alo[ks], sb + COFF_ALO + rrow*(RPAD*2) + ks*32 + rchk);
        }
    }
    __syncthreads();   // all warps done reading A smem

    // prefetch chunk1 (global rows 104..195) into dead A region via cp.async;
    // zero-pad local rows 92..95 with regular stores
    {
        uint4 z = make_uint4(0,0,0,0);
        for (int idx=tid; idx<4*13; idx+=256) {
            int r = 92 + idx/13, q = idx%13;
            *(uint4*)(smem + COFF_AHI + (r*13+q)*16) = z;
            *(uint4*)(smem + COFF_ALO + (r*13+q)*16) = z;
        }
        for (int idx=tid; idx<92*12; idx+=256) {
            int r = idx/12, q = idx%12;
            CP_ASYNC16(sb + COFF_AHI + (r*13+q)*16, (const void*)(Bh + (104+r)*12 + q));
            CP_ASYNC16(sb + COFF_ALO + (r*13+q)*16, (const void*)(Bl + (104+r)*12 + q));
        }
        CP_COMMIT();
    }

    float mbest = -1e30f;
    int brow = lane & 7;
    int bqd  = ((lane >> 3) & 3) * 16;

    // ---- chunk 0: nt 0..12 (cols 0..103, all valid), prefetched B frags ----
    {
        uint32_t pbh[2][4], pbl[2][4];
        ldsm_x4(pbh[0], sb + COFF_BHI + brow*(RPAD*2) + bqd);
        ldsm_x4(pbl[0], sb + COFF_BLO + brow*(RPAD*2) + bqd);
#pragma unroll
        for (int nt=0; nt<13; nt++) {
            float a0[4]={0.f,0.f,0.f,0.f}, a1[4]={0.f,0.f,0.f,0.f};
#pragma unroll
            for (int ks2=0; ks2<3; ks2++) {
                int it = nt*3 + ks2;
                int cur = it & 1;
                if (it < 38) {
                    int itn = it + 1;
                    int ntn = itn/3, ks2n = itn - ntn*3;
                    uint32_t bb = (ntn*8+brow)*(RPAD*2) + bqd + ks2n*64;
                    ldsm_x4(pbh[cur^1], sb + COFF_BHI + bb);
                    ldsm_x4(pbl[cur^1], sb + COFF_BLO + bb);
                }
                mma16816(a0, ahi[2*ks2],   pbh[cur]);
                mma16816(a1, alo[2*ks2],   pbh[cur]);
                mma16816(a0, ahi[2*ks2],   pbl[cur]);
                mma16816(a1, ahi[2*ks2+1], pbh[cur]+2);
                mma16816(a0, alo[2*ks2+1], pbh[cur]+2);
                mma16816(a1, ahi[2*ks2+1], pbl[cur]+2);
            }
            mbest = fmaxf(mbest, fmaxf(fmaxf(a0[0]+a1[0], a0[1]+a1[1]),
                                       fmaxf(a0[2]+a1[2], a0[3]+a1[3])));
        }
    }

    CP_WAIT0();
    __syncthreads();

    // ---- chunk 1: nt 13..24 from A region (global cols 104..199; mask >=196) ----
    {
        uint32_t pbh[2][4], pbl[2][4];
        ldsm_x4(pbh[0], sb + COFF_AHI + brow*(RPAD*2) + bqd);
        ldsm_x4(pbl[0], sb + COFF_ALO + brow*(RPAD*2) + bqd);
#pragma unroll
        for (int nt=13; nt<25; nt++) {
            float a0[4]={0.f,0.f,0.f,0.f}, a1[4]={0.f,0.f,0.f,0.f};
            int lnt = nt - 13;
#pragma unroll
            for (int ks2=0; ks2<3; ks2++) {
                int it = lnt*3 + ks2;
                int cur = it & 1;
                if (it < 35) {
                    int itn = it + 1;
                    int ntn = itn/3, ks2n = itn - ntn*3;
                    uint32_t bb = (ntn*8+brow)*(RPAD*2) + bqd + ks2n*64;
                    ldsm_x4(pbh[cur^1], sb + COFF_AHI + bb);
                    ldsm_x4(pbl[cur^1], sb + COFF_ALO + bb);
                }
                mma16816(a0, ahi[2*ks2],   pbh[cur]);
                mma16816(a1, alo[2*ks2],   pbh[cur]);
                mma16816(a0, ahi[2*ks2],   pbl[cur]);
                mma16816(a1, ahi[2*ks2+1], pbh[cur]+2);
                mma16816(a0, alo[2*ks2+1], pbh[cur]+2);
                mma16816(a1, ahi[2*ks2+1], pbl[cur]+2);
            }
            int col0 = nt*8 + (lane & 3)*2;
            if (col0 < PLEN)   mbest = fmaxf(mbest, fmaxf(a0[0]+a1[0], a0[2]+a1[2]));
            if (col0+1 < PLEN) mbest = fmaxf(mbest, fmaxf(a0[1]+a1[1], a0[3]+a1[3]));
        }
    }

#pragma unroll
    for (int o=16;o;o>>=1) mbest = fmaxf(mbest, __shfl_xor_sync(0xffffffffu,mbest,o));
    float* red = (float*)(smem + COFF_RED);
    if (lane == 0) red[wid] = mbest;
    __syncthreads();
    if (tid == 0) {
        float m = red[0];
#pragma unroll
        for (int w=1;w<8;w++) m = fmaxf(m, red[w]);
        out[b*64+c] += 0.5f*m;
    }
}

// ---------------- host ----------------
extern "C" void kernel_launch(void* const* d_in, const int* in_sizes, int n_in,
                              void* d_out, int out_size)
{
    const float* z_d_cls = (const float*)d_in[0];
    const float* Z_d_tok = (const float*)d_in[1];
    const float* z_t_cls = (const float*)d_in[2];
    const float* Z_t_tok = (const float*)d_in[3];
    const float* z_v_cls = (const float*)d_in[4];
    const float* Z_v_pat = (const float*)d_in[5];
    const float *W_t_cls=(const float*)d_in[6],  *b_t_cls=(const float*)d_in[7];
    const float *W_d_cls=(const float*)d_in[8],  *b_d_cls=(const float*)d_in[9];
    const float *W_v_cls=(const float*)d_in[10], *b_v_cls=(const float*)d_in[11];
    const float *W_t_tok=(const float*)d_in[12], *b_t_tok=(const float*)d_in[13];
    const float *W_v_pat=(const float*)d_in[14], *b_v_pat=(const float*)d_in[15];
    const float *W_q=(const float*)d_in[16], *b_q=(const float*)d_in[17];
    const float *W_k=(const float*)d_in[18], *b_k=(const float*)d_in[19];
    const float *W_v=(const float*)d_in[20], *b_v=(const float*)d_in[21];
    const float *ln_g=(const float*)d_in[22], *ln_b=(const float*)d_in[23];
    float* out = (float*)d_out;

    float *Vp,*tp,*dp,*vp;
    void *qhi,*qlo,*khi,*klo,*ahi,*alo,*bhi,*blo;
    cudaGetSymbolAddress((void**)&Vp,  g_Vt);
    cudaGetSymbolAddress((void**)&tp,  g_t);
    cudaGetSymbolAddress((void**)&dp,  g_d);
    cudaGetSymbolAddress((void**)&vp,  g_v);
    cudaGetSymbolAddress(&qhi, g_Qhi);
    cudaGetSymbolAddress(&qlo, g_Qlo);
    cudaGetSymbolAddress(&khi, g_Khi);
    cudaGetSymbolAddress(&klo, g_Klo);
    cudaGetSymbolAddress(&ahi, g_Ahi);
    cudaGetSymbolAddress(&alo, g_Alo);
    cudaGetSymbolAddress(&bhi, g_Bhi);
    cudaGetSymbolAddress(&blo, g_Blo);

    cudaFuncSetAttribute(proj_mma, cudaFuncAttributeMaxDynamicSharedMemorySize, SM_PROJ);
    cudaFuncSetAttribute(tgl_mma,  cudaFuncAttributeMaxDynamicSharedMemorySize, SM_TGL);
    cudaFuncSetAttribute(cll_mma,  cudaFuncAttributeMaxDynamicSharedMemorySize, SM_CLL);

    ProjArgs pa;
    for (int i=0;i<8;i++) { pa.Out2[i]=nullptr; pa.mode[i]=0; pa.L[i]=0; pa.l2n[i]=0; }
    pa.X[0]=Z_d_tok; pa.W[0]=W_q;     pa.Bv[0]=b_q;     pa.Out[0]=(float*)qhi; pa.Out2[0]=qlo; pa.mode[0]=1;
    pa.X[1]=Z_t_tok; pa.W[1]=W_k;     pa.Bv[1]=b_k;     pa.Out[1]=(float*)khi; pa.Out2[1]=klo; pa.mode[1]=1;
    pa.X[2]=Z_t_tok; pa.W[2]=W_v;     pa.Bv[2]=b_v;     pa.Out[2]=Vp;  pa.L[2]=QLEN;
    pa.X[3]=Z_t_tok; pa.W[3]=W_t_tok; pa.Bv[3]=b_t_tok; pa.Out[3]=(float*)ahi; pa.Out2[3]=alo; pa.l2n[3]=1; pa.mode[3]=1;
    pa.X[4]=Z_v_pat; pa.W[4]=W_v_pat; pa.Bv[4]=b_v_pat; pa.Out[4]=(float*)bhi; pa.Out2[4]=blo; pa.l2n[4]=1; pa.mode[4]=2;
    pa.X[5]=z_t_cls; pa.W[5]=W_t_cls; pa.Bv[5]=b_t_cls; pa.Out[5]=tp;  pa.l2n[5]=1;
    pa.X[6]=z_d_cls; pa.W[6]=W_d_cls; pa.Bv[6]=b_d_cls; pa.Out[6]=dp;  pa.l2n[6]=1;
    pa.X[7]=z_v_cls; pa.W[7]=W_v_cls; pa.Bv[7]=b_v_cls; pa.Out[7]=vp;  pa.l2n[7]=1;
    int nt[8] = {128,128,128,128,196,1,1,1};
    pa.tile_start[0]=0;
    for (int i=0;i<8;i++) pa.tile_start[i+1]=pa.tile_start[i]+nt[i];

    proj_mma<<<pa.tile_start[8],256,SM_PROJ>>>(pa);

    // out = 0.5*(S_TGG + S_CGG + S_TGL)   (gg folded, "=" write)
    tgl_mma<<<dim3(64,64),256,SM_TGL>>>(ln_g, ln_b, out);
    // out += 0.5*S_CLL
    cll_mma<<<dim3(64,64),256,SM_CLL>>>(out);
}